// round 12
// baseline (speedup 1.0000x reference)
#include <cuda_runtime.h>
#include <cuda_fp16.h>
#include <math.h>
#include <stdint.h>

// ---------------- problem constants ----------------
constexpr int B_ = 8, C_ = 512, H_ = 96, W_ = 96;
constexpr int N_ = H_ * W_;    // 9216
constexpr int O3 = 3 * C_;     // 1536

// ---------------- scratch: fp16 planes ----------------
__device__ __align__(256) __half g_qh [(size_t)B_ * O3 * N_];   // qkv hi
__device__ __align__(256) __half g_ql [(size_t)B_ * O3 * N_];   // qkv lo
__device__ __align__(256) __half g_xTh[(size_t)B_ * N_ * C_];   // xT hi; later o1T hi
__device__ __align__(256) __half g_vTh[(size_t)B_ * N_ * C_];
__device__ __align__(256) __half g_vTl[(size_t)B_ * N_ * C_];
__device__ __align__(256) float  g_S  [(size_t)B_ * C_ * C_];
__device__ __align__(256) __half g_ah [(size_t)B_ * C_ * C_];   // attn hi
__device__ __align__(256) __half g_wqh[(size_t)O3 * C_];
__device__ __align__(256) __half g_wph[(size_t)C_ * C_];
__device__ __align__(256) __half g_wpl[(size_t)C_ * C_];

// ---------------- common helpers ----------------
#define BK 64
#define LDT 72   // smem row stride in halves (BK + 8 pad)

__device__ __forceinline__ uint32_t smem_u32(const void* p) {
    uint32_t a;
    asm("{ .reg .u64 t; cvta.to.shared.u64 t, %1; cvt.u32.u64 %0, t; }"
        : "=r"(a) : "l"(p));
    return a;
}
__device__ __forceinline__ void cp16(uint32_t dst, const void* src) {
    asm volatile("cp.async.cg.shared.global [%0], [%1], 16;"
                 :: "r"(dst), "l"(src));
}
__device__ __forceinline__ void mma16816(float* d, const uint32_t* a,
                                         const uint32_t* b) {
    asm volatile(
        "mma.sync.aligned.m16n8k16.row.col.f32.f16.f16.f32 "
        "{%0,%1,%2,%3}, {%4,%5,%6,%7}, {%8,%9}, {%0,%1,%2,%3};"
        : "+f"(d[0]), "+f"(d[1]), "+f"(d[2]), "+f"(d[3])
        : "r"(a[0]), "r"(a[1]), "r"(a[2]), "r"(a[3]), "r"(b[0]), "r"(b[1]));
}
__device__ __forceinline__ void ldm4(uint32_t* r, uint32_t a) {
    asm volatile("ldmatrix.sync.aligned.m8n8.x4.shared.b16 {%0,%1,%2,%3}, [%4];"
        : "=r"(r[0]), "=r"(r[1]), "=r"(r[2]), "=r"(r[3]) : "r"(a));
}
__device__ __forceinline__ uint32_t pack2h(__half a, __half b) {
    return (uint32_t)__half_as_ushort(a) |
           ((uint32_t)__half_as_ushort(b) << 16);
}
__device__ __forceinline__ void split2h(float f, __half& h, __half& l) {
    h = __float2half(f);
    l = __float2half(f - __half2float(h));
}

// lane offsets (half elem units) for ldmatrix addressing
__device__ __forceinline__ int laneA_off(int lane) {
    return ((lane & 7) + ((lane >> 3) & 1) * 8) * LDT + ((lane >> 4) & 1) * 8;
}
__device__ __forceinline__ int laneB_off(int lane) {
    return ((lane & 7) + ((lane >> 4) & 1) * 8) * LDT + ((lane >> 3) & 1) * 8;
}

// 1-pass compute body: ah * bh  (one K=16 step)
__device__ __forceinline__ void compute_ks1(float acc[4][4][4],
                                            uint32_t aHi, uint32_t bHi)
{
    uint32_t ah[4][4], bh[2][4];
    #pragma unroll
    for (int i = 0; i < 4; i++) ldm4(ah[i], aHi + i * (16 * LDT * 2));
    #pragma unroll
    for (int jp = 0; jp < 2; jp++) ldm4(bh[jp], bHi + jp * (16 * LDT * 2));
    #pragma unroll
    for (int i = 0; i < 4; i++) {
        mma16816(acc[i][0], ah[i], bh[0]);
        mma16816(acc[i][1], ah[i], bh[0] + 2);
        mma16816(acc[i][2], ah[i], bh[1]);
        mma16816(acc[i][3], ah[i], bh[1] + 2);
    }
}

// 2-pass compute body: (ah + al) * bh  (one K=16 step)
__device__ __forceinline__ void compute_ks2(float acc[4][4][4],
                                            uint32_t aHi, uint32_t aLo,
                                            uint32_t bHi)
{
    uint32_t ah[4][4], al_[4][4], bh[2][4];
    #pragma unroll
    for (int i = 0; i < 4; i++) ldm4(ah[i], aHi + i * (16 * LDT * 2));
    #pragma unroll
    for (int jp = 0; jp < 2; jp++) ldm4(bh[jp], bHi + jp * (16 * LDT * 2));
    #pragma unroll
    for (int i = 0; i < 4; i++) {
        ldm4(al_[i], aLo + i * (16 * LDT * 2));
        mma16816(acc[i][0], ah[i], bh[0]);
        mma16816(acc[i][1], ah[i], bh[0] + 2);
        mma16816(acc[i][2], ah[i], bh[1]);
        mma16816(acc[i][3], ah[i], bh[1] + 2);
    }
    #pragma unroll
    for (int i = 0; i < 4; i++) {
        mma16816(acc[i][0], al_[i], bh[0]);
        mma16816(acc[i][1], al_[i], bh[0] + 2);
        mma16816(acc[i][2], al_[i], bh[1]);
        mma16816(acc[i][3], al_[i], bh[1] + 2);
    }
}

// ============== BIG kernel: 128x256, 512 thr, BK=64 =======================
// OUTMODE: 0 = f32, 1 = split hi/lo fp16, 2 = hi-only fp16
// PASSES:  1 = ah*bh (3-stage) ; 2 = (ah+al)*bh (2-stage)
#define BM2 128
#define BN2 256

template<bool HASBIAS, int OUTMODE, int PASSES>
__global__ __launch_bounds__(512)
void gemm_big(const __half* __restrict__ Ah, const __half* __restrict__ Al,
              const __half* __restrict__ Bh,
              float* __restrict__ Cf,
              __half* __restrict__ Ch, __half* __restrict__ Cl,
              const float* __restrict__ bias,
              int K, int lda, int ldb, int ldc,
              size_t sA_, size_t sB_, size_t sC_)
{
    constexpr int NST      = (PASSES == 2) ? 2 : 3;
    constexpr int SROWS    = (PASSES == 2) ? 512 : 384;
    constexpr uint32_t AL2 = 128 * LDT * 2;                          // A-lo plane byte off
    constexpr uint32_t BH2 = ((PASSES == 2) ? 256 : 128) * LDT * 2;  // B plane byte off
    constexpr uint32_t STAGE_BY = SROWS * LDT * 2;

    extern __shared__ __half smem[];
    const int tid  = threadIdx.x;
    const int warp = tid >> 5;
    const int lane = tid & 31;
    const int wm   = (warp >> 3) * 64;   // 2 warps in M
    const int wn   = (warp & 7) * 32;    // 8 warps in N
    const int tm   = blockIdx.y * BM2;
    const int tn   = blockIdx.x * BN2;

    const __half* Ahb = Ah + (size_t)blockIdx.z * sA_;
    const __half* Alb = (PASSES == 2) ? Al + (size_t)blockIdx.z * sA_ : nullptr;
    const __half* Bhb = Bh + (size_t)blockIdx.z * sB_;

    // cp.async mapping: row = tid>>3 (+64*i), granule = (tid&7)*8 halves
    const int r0 = tid >> 3, g8 = (tid & 7) * 8;
    const __half* pAh0 = Ahb + (size_t)(tm + r0) * lda + g8;
    const __half* pAh1 = pAh0 + (size_t)64 * lda;
    const __half* pAl0 = (PASSES == 2) ? Alb + (size_t)(tm + r0) * lda + g8 : nullptr;
    const __half* pAl1 = (PASSES == 2) ? pAl0 + (size_t)64 * lda : nullptr;
    const __half* pB0  = Bhb + (size_t)(tn + r0) * ldb + g8;
    const __half* pB1  = pB0 + (size_t)64  * ldb;
    const __half* pB2  = pB0 + (size_t)128 * ldb;
    const __half* pB3  = pB0 + (size_t)192 * ldb;

    const uint32_t sbase = smem_u32(smem);
    const uint32_t o0   = (r0 * LDT + g8) * 2;
    const uint32_t o64  = o0 + 64  * LDT * 2;
    const uint32_t o128 = o0 + 128 * LDT * 2;
    const uint32_t o192 = o0 + 192 * LDT * 2;

    const int lA = laneA_off(lane);
    const int lB = laneB_off(lane);

    float acc[4][4][4];
    #pragma unroll
    for (int i = 0; i < 4; i++)
        #pragma unroll
        for (int j = 0; j < 4; j++)
            #pragma unroll
            for (int t = 0; t < 4; t++) acc[i][j][t] = 0.f;

    auto issue = [&](int c) {
        const uint32_t sb = sbase + (c % NST) * STAGE_BY;
        const int k0 = c * BK;
        cp16(sb + o0,  pAh0 + k0);
        cp16(sb + o64, pAh1 + k0);
        if (PASSES == 2) {
            cp16(sb + AL2 + o0,  pAl0 + k0);
            cp16(sb + AL2 + o64, pAl1 + k0);
        }
        cp16(sb + BH2 + o0,   pB0 + k0);
        cp16(sb + BH2 + o64,  pB1 + k0);
        cp16(sb + BH2 + o128, pB2 + k0);
        cp16(sb + BH2 + o192, pB3 + k0);
    };

    const int nc = K / BK;
    #pragma unroll
    for (int s = 0; s < NST - 1; s++) {
        issue(s);
        asm volatile("cp.async.commit_group;");
    }

    for (int c = 0; c < nc; ++c) {
        if (NST == 3) asm volatile("cp.async.wait_group 1;");
        else          asm volatile("cp.async.wait_group 0;");
        __syncthreads();
        if (c + NST - 1 < nc) issue(c + NST - 1);
        asm volatile("cp.async.commit_group;");

        const uint32_t stb = sbase + (c % NST) * STAGE_BY;
        const uint32_t aH0 = stb + (wm * LDT + lA) * 2;
        const uint32_t aL0 = stb + AL2 + (wm * LDT + lA) * 2;
        const uint32_t bH0 = stb + BH2 + (wn * LDT + lB) * 2;
        #pragma unroll
        for (int ks = 0; ks < 4; ++ks) {
            const uint32_t ko = ks * 32;   // 16 halves = 32 bytes
            if (PASSES == 2) compute_ks2(acc, aH0 + ko, aL0 + ko, bH0 + ko);
            else             compute_ks1(acc, aH0 + ko, bH0 + ko);
        }
    }

    // ---------------- epilogue ----------------
    #pragma unroll
    for (int i = 0; i < 4; i++) {
        const int r = tm + wm + i * 16 + (lane >> 2);
        float bv0 = 0.f, bv1 = 0.f;
        if (HASBIAS) { bv0 = bias[r]; bv1 = bias[r + 8]; }
        #pragma unroll
        for (int j = 0; j < 4; j++) {
            const int cc = tn + wn + j * 8 + (lane & 3) * 2;
            float d0 = acc[i][j][0] + bv0, d1 = acc[i][j][1] + bv0;
            float d2 = acc[i][j][2] + bv1, d3 = acc[i][j][3] + bv1;
            if (OUTMODE == 0) {
                float* cfp = Cf + (size_t)blockIdx.z * sC_;
                *reinterpret_cast<float2*>(&cfp[(size_t)r * ldc + cc])       = make_float2(d0, d1);
                *reinterpret_cast<float2*>(&cfp[(size_t)(r + 8) * ldc + cc]) = make_float2(d2, d3);
            } else if (OUTMODE == 1) {
                __half* chp = Ch + (size_t)blockIdx.z * sC_;
                __half* clp = Cl + (size_t)blockIdx.z * sC_;
                __half h0, h1, h2, h3, l0, l1, l2, l3;
                split2h(d0, h0, l0); split2h(d1, h1, l1);
                split2h(d2, h2, l2); split2h(d3, h3, l3);
                *reinterpret_cast<uint32_t*>(&chp[(size_t)r * ldc + cc])       = pack2h(h0, h1);
                *reinterpret_cast<uint32_t*>(&clp[(size_t)r * ldc + cc])       = pack2h(l0, l1);
                *reinterpret_cast<uint32_t*>(&chp[(size_t)(r + 8) * ldc + cc]) = pack2h(h2, h3);
                *reinterpret_cast<uint32_t*>(&clp[(size_t)(r + 8) * ldc + cc]) = pack2h(l2, l3);
            } else {
                __half* chp = Ch + (size_t)blockIdx.z * sC_;
                *reinterpret_cast<uint32_t*>(&chp[(size_t)r * ldc + cc]) =
                    pack2h(__float2half(d0), __float2half(d1));
                *reinterpret_cast<uint32_t*>(&chp[(size_t)(r + 8) * ldc + cc]) =
                    pack2h(__float2half(d2), __float2half(d3));
            }
        }
    }
}

// ====== S kernel: 128x128, 256 thr, BK=64, 2-stage, 2-pass ================
#define S_AL (128 * LDT * 2)
#define S_BH (256 * LDT * 2)
#define S_STAGE_BY (384 * LDT * 2)            // 55296 B
#define SMEM_BYS (2 * S_STAGE_BY)             // 110592 B

__global__ __launch_bounds__(256)
void gemm_s(const __half* __restrict__ Ah, const __half* __restrict__ Al,
            const __half* __restrict__ Bh,
            float* __restrict__ Cf,
            int K, int lda, int ldb, int ldc,
            size_t sA_, size_t sB_, size_t sC_)
{
    extern __shared__ __half smem[];
    const int tid  = threadIdx.x;
    const int warp = tid >> 5;
    const int lane = tid & 31;
    const int wm   = (warp >> 2) * 64;
    const int wn   = (warp & 3) * 32;
    const int tm   = blockIdx.y * 128;
    const int tn   = blockIdx.x * 128;

    const __half* Ahb = Ah + (size_t)blockIdx.z * sA_;
    const __half* Alb = Al + (size_t)blockIdx.z * sA_;
    const __half* Bhb = Bh + (size_t)blockIdx.z * sB_;

    // 256 threads: row = tid>>3 (+32*i), granule = (tid&7)*8 halves
    const int r0 = tid >> 3, g8 = (tid & 7) * 8;
    const uint32_t sbase = smem_u32(smem);
    const uint32_t oo[4] = {
        (uint32_t)((r0 * LDT + g8) * 2),
        (uint32_t)(((r0 + 32) * LDT + g8) * 2),
        (uint32_t)(((r0 + 64) * LDT + g8) * 2),
        (uint32_t)(((r0 + 96) * LDT + g8) * 2)
    };
    const __half* pA[4];
    const __half* pL[4];
    const __half* pB[4];
    #pragma unroll
    for (int i = 0; i < 4; i++) {
        pA[i] = Ahb + (size_t)(tm + r0 + 32 * i) * lda + g8;
        pL[i] = Alb + (size_t)(tm + r0 + 32 * i) * lda + g8;
        pB[i] = Bhb + (size_t)(tn + r0 + 32 * i) * ldb + g8;
    }

    const int lA = laneA_off(lane);
    const int lB = laneB_off(lane);

    float acc[4][4][4];
    #pragma unroll
    for (int i = 0; i < 4; i++)
        #pragma unroll
        for (int j = 0; j < 4; j++)
            #pragma unroll
            for (int t = 0; t < 4; t++) acc[i][j][t] = 0.f;

    auto issue = [&](int c) {
        const uint32_t sb = sbase + (c & 1) * S_STAGE_BY;
        const int k0 = c * BK;
        #pragma unroll
        for (int i = 0; i < 4; i++) {
            cp16(sb + oo[i],        pA[i] + k0);
            cp16(sb + S_AL + oo[i], pL[i] + k0);
            cp16(sb + S_BH + oo[i], pB[i] + k0);
        }
    };

    const int nc = K / BK;
    issue(0);
    asm volatile("cp.async.commit_group;");

    for (int c = 0; c < nc; ++c) {
        asm volatile("cp.async.wait_group 0;");
        __syncthreads();
        if (c + 1 < nc) issue(c + 1);
        asm volatile("cp.async.commit_group;");

        const uint32_t stb = sbase + (c & 1) * S_STAGE_BY;
        const uint32_t aH0 = stb + (wm * LDT + lA) * 2;
        const uint32_t aL0 = stb + S_AL + (wm * LDT + lA) * 2;
        const uint32_t bH0 = stb + S_BH + (wn * LDT + lB) * 2;
        #pragma unroll
        for (int ks = 0; ks < 4; ++ks) {
            const uint32_t ko = ks * 32;
            compute_ks2(acc, aH0 + ko, aL0 + ko, bH0 + ko);
        }
    }

    float* cfp = Cf + (size_t)blockIdx.z * sC_;
    #pragma unroll
    for (int i = 0; i < 4; i++) {
        const int r = tm + wm + i * 16 + (lane >> 2);
        #pragma unroll
        for (int j = 0; j < 4; j++) {
            const int cc = tn + wn + j * 8 + (lane & 3) * 2;
            *reinterpret_cast<float2*>(&cfp[(size_t)r * ldc + cc]) =
                make_float2(acc[i][j][0], acc[i][j][1]);
            *reinterpret_cast<float2*>(&cfp[(size_t)(r + 8) * ldc + cc]) =
                make_float2(acc[i][j][2], acc[i][j][3]);
        }
    }
}

// ------------- transpose fp32 [R,Cc] -> fp16 hi [Cc,R] ---------------------
__global__ void transpose_hi(const float* __restrict__ in,
                             __half* __restrict__ oh,
                             int R, int Cc, size_t sIn, size_t sOut)
{
    __shared__ float t[32][33];
    const float* ip = in + (size_t)blockIdx.z * sIn;
    int r0 = blockIdx.y * 32, c0 = blockIdx.x * 32;
    #pragma unroll
    for (int j = threadIdx.y; j < 32; j += 8)
        t[j][threadIdx.x] = ip[(size_t)(r0 + j) * Cc + c0 + threadIdx.x];
    __syncthreads();
    #pragma unroll
    for (int j = threadIdx.y; j < 32; j += 8) {
        size_t idx = (size_t)blockIdx.z * sOut + (size_t)(c0 + j) * R + r0 + threadIdx.x;
        oh[idx] = __float2half(t[threadIdx.x][j]);
    }
}

// ------------- transpose two fp16 planes: [R,Cc] -> [Cc,R] -----------------
__global__ void transpose_h2(const __half* __restrict__ ih,
                             const __half* __restrict__ il,
                             __half* __restrict__ oh,
                             __half* __restrict__ ol,
                             int R, int Cc, size_t sIn, size_t sOut)
{
    __shared__ __half th[32][34], tl[32][34];
    const __half* ihp = ih + (size_t)blockIdx.z * sIn;
    const __half* ilp = il + (size_t)blockIdx.z * sIn;
    int r0 = blockIdx.y * 32, c0 = blockIdx.x * 32;
    #pragma unroll
    for (int j = threadIdx.y; j < 32; j += 8) {
        size_t s = (size_t)(r0 + j) * Cc + c0 + threadIdx.x;
        th[j][threadIdx.x] = ihp[s];
        tl[j][threadIdx.x] = ilp[s];
    }
    __syncthreads();
    #pragma unroll
    for (int j = threadIdx.y; j < 32; j += 8) {
        size_t d = (size_t)blockIdx.z * sOut + (size_t)(c0 + j) * R + r0 + threadIdx.x;
        oh[d] = th[threadIdx.x][j];
        ol[d] = tl[threadIdx.x][j];
    }
}

// ------------- elementwise casts ------------------------------------------
__global__ void split_w(const float* __restrict__ in,
                        __half* __restrict__ oh,
                        __half* __restrict__ ol, int n)
{
    int i = blockIdx.x * blockDim.x + threadIdx.x;
    if (i >= n) return;
    __half h, l;
    split2h(in[i], h, l);
    oh[i] = h;
    ol[i] = l;
}
__global__ void cast_hi(const float* __restrict__ in,
                        __half* __restrict__ oh, int n)
{
    int i = blockIdx.x * blockDim.x + threadIdx.x;
    if (i >= n) return;
    oh[i] = __float2half(in[i]);
}

// ------------- softmax (fp32 in, fp16 hi out), rows of 512 -----------------
__global__ void softmax_hi(const float* __restrict__ S,
                           __half* __restrict__ oh, float scale)
{
    int warp = (blockIdx.x * blockDim.x + threadIdx.x) >> 5;
    int lane = threadIdx.x & 31;
    if (warp >= B_ * C_) return;
    const float* row = S + (size_t)warp * C_;

    float vals[C_ / 32];
    float m = -1e30f;
    #pragma unroll
    for (int t = 0; t < C_ / 32; t++) {
        vals[t] = row[lane + t * 32] * scale;
        m = fmaxf(m, vals[t]);
    }
    #pragma unroll
    for (int o = 16; o; o >>= 1) m = fmaxf(m, __shfl_xor_sync(0xffffffffu, m, o));
    float s = 0.f;
    #pragma unroll
    for (int t = 0; t < C_ / 32; t++) { vals[t] = __expf(vals[t] - m); s += vals[t]; }
    #pragma unroll
    for (int o = 16; o; o >>= 1) s += __shfl_xor_sync(0xffffffffu, s, o);
    float inv = 1.f / s;
    #pragma unroll
    for (int t = 0; t < C_ / 32; t++)
        oh[(size_t)warp * C_ + lane + t * 32] = __float2half(vals[t] * inv);
}

// ---------------- launcher ----------------
extern "C" void kernel_launch(void* const* d_in, const int* in_sizes, int n_in,
                              void* d_out, int out_size)
{
    const float* x      = (const float*)d_in[0];
    const float* w_qkv  = (const float*)d_in[1];
    const float* b_qkv  = (const float*)d_in[2];
    const float* w_proj = (const float*)d_in[3];
    const float* b_proj = (const float*)d_in[4];
    float* out = (float*)d_out;

    __half *qh, *ql, *xTh, *vTh, *vTl, *ah, *wqh, *wph, *wpl;
    float *S;
    cudaGetSymbolAddress((void**)&qh,  g_qh);
    cudaGetSymbolAddress((void**)&ql,  g_ql);
    cudaGetSymbolAddress((void**)&xTh, g_xTh);
    cudaGetSymbolAddress((void**)&vTh, g_vTh);
    cudaGetSymbolAddress((void**)&vTl, g_vTl);
    cudaGetSymbolAddress((void**)&S,   g_S);
    cudaGetSymbolAddress((void**)&ah,  g_ah);
    cudaGetSymbolAddress((void**)&wqh, g_wqh);
    cudaGetSymbolAddress((void**)&wph, g_wph);
    cudaGetSymbolAddress((void**)&wpl, g_wpl);

    // smem sizes: 1-pass big = 3 stages * 384 rows; 2-pass big = 2 * 512 rows
    const int SM_BIG1 = 3 * 384 * LDT * 2;   // 165888
    const int SM_BIG2 = 2 * 512 * LDT * 2;   // 147456
    cudaFuncSetAttribute(gemm_big<true,  1, 1>, cudaFuncAttributeMaxDynamicSharedMemorySize, SM_BIG1);
    cudaFuncSetAttribute(gemm_big<false, 2, 2>, cudaFuncAttributeMaxDynamicSharedMemorySize, SM_BIG2);
    cudaFuncSetAttribute(gemm_big<true,  0, 2>, cudaFuncAttributeMaxDynamicSharedMemorySize, SM_BIG2);
    cudaFuncSetAttribute(gemm_s, cudaFuncAttributeMaxDynamicSharedMemorySize, SMEM_BYS);

    const float scale = 1.0f / sqrtf((float)C_);
    dim3 tblk(32, 8);

    // 0) weights: qkv hi only (1-pass GEMM), proj hi/lo (2-pass GEMM)
    cast_hi<<<(O3 * C_ + 255) / 256, 256>>>(w_qkv, wqh, O3 * C_);
    split_w<<<(C_ * C_ + 255) / 256, 256>>>(w_proj, wph, wpl, C_ * C_);

    // 1) xT hi: x[b,c,n] -> [b,n,c]
    transpose_hi<<<dim3(N_ / 32, C_ / 32, B_), tblk>>>(
        x, xTh, C_, N_, (size_t)C_ * N_, (size_t)N_ * C_);

    // 2) qkv = w_qkv @ xT^T + b  (1-pass) -> fp16 hi/lo
    gemm_big<true, 1, 1><<<dim3(N_ / BN2, O3 / BM2, B_), 512, SM_BIG1>>>(
        wqh, nullptr, xTh, nullptr, qh, ql, b_qkv,
        C_, C_, C_, N_,
        0, (size_t)N_ * C_, (size_t)O3 * N_);

    // 3) vT hi/lo: v[b,d,n] -> [b,n,d]
    transpose_h2<<<dim3(N_ / 32, C_ / 32, B_), tblk>>>(
        qh + (size_t)2 * C_ * N_, ql + (size_t)2 * C_ * N_, vTh, vTl,
        C_, N_, (size_t)O3 * N_, (size_t)N_ * C_);

    // 4) S = q @ k^T (2-pass, K=9216) -> fp32
    gemm_s<<<dim3(C_ / 128, C_ / 128, B_), 256, SMEM_BYS>>>(
        qh, ql, qh + (size_t)C_ * N_, S,
        N_, N_, N_, C_,
        (size_t)O3 * N_, (size_t)O3 * N_, (size_t)C_ * C_);

    // 5) softmax -> attn hi
    softmax_hi<<<(B_ * C_ * 32 + 255) / 256, 256>>>(S, ah, scale);

    // 6) o1T[b,n,c] = vT[b,n,:] @ attn[b,c,:]  (2-pass) -> hi only (reuse xTh)
    gemm_big<false, 2, 2><<<dim3(C_ / BN2, N_ / BM2, B_), 512, SM_BIG2>>>(
        vTh, vTl, ah, nullptr, xTh, nullptr, nullptr,
        C_, C_, C_, C_,
        (size_t)N_ * C_, (size_t)C_ * C_, (size_t)N_ * C_);

    // 7) out = w_proj @ o1T^T + b  (2-pass) -> fp32
    gemm_big<true, 0, 2><<<dim3(N_ / BN2, C_ / BM2, B_), 512, SM_BIG2>>>(
        wph, wpl, xTh, out, nullptr, nullptr, b_proj,
        C_, C_, C_, N_,
        0, (size_t)N_ * C_, (size_t)C_ * N_);
}

// round 13
// speedup vs baseline: 1.3717x; 1.3717x over previous
#include <cuda_runtime.h>
#include <cuda_fp16.h>
#include <math.h>
#include <stdint.h>

// ---------------- problem constants ----------------
constexpr int B_ = 8, C_ = 512, H_ = 96, W_ = 96;
constexpr int N_ = H_ * W_;    // 9216
constexpr int O3 = 3 * C_;     // 1536
constexpr int KSPLIT = 4;      // split-K factor for the S GEMM

// ---------------- scratch: fp16 planes ----------------
__device__ __align__(256) __half g_qh [(size_t)B_ * O3 * N_];   // qkv hi
__device__ __align__(256) __half g_ql [(size_t)B_ * O3 * N_];   // qkv lo
__device__ __align__(256) __half g_xTh[(size_t)B_ * N_ * C_];   // xT hi; later o1T hi
__device__ __align__(256) __half g_vTh[(size_t)B_ * N_ * C_];
__device__ __align__(256) __half g_vTl[(size_t)B_ * N_ * C_];
__device__ __align__(256) float  g_Sp [(size_t)KSPLIT * B_ * C_ * C_];  // split-K partials
__device__ __align__(256) __half g_ah [(size_t)B_ * C_ * C_];   // attn hi
__device__ __align__(256) __half g_wqh[(size_t)O3 * C_];
__device__ __align__(256) __half g_wph[(size_t)C_ * C_];
__device__ __align__(256) __half g_wpl[(size_t)C_ * C_];

// ---------------- common helpers ----------------
#define BK 32
#define LDT 40   // smem row stride in halves (BK + 8 pad)

__device__ __forceinline__ uint32_t smem_u32(const void* p) {
    uint32_t a;
    asm("{ .reg .u64 t; cvta.to.shared.u64 t, %1; cvt.u32.u64 %0, t; }"
        : "=r"(a) : "l"(p));
    return a;
}
__device__ __forceinline__ void cp16(uint32_t dst, const void* src) {
    asm volatile("cp.async.cg.shared.global [%0], [%1], 16;"
                 :: "r"(dst), "l"(src));
}
__device__ __forceinline__ void mma16816(float* d, const uint32_t* a,
                                         const uint32_t* b) {
    asm volatile(
        "mma.sync.aligned.m16n8k16.row.col.f32.f16.f16.f32 "
        "{%0,%1,%2,%3}, {%4,%5,%6,%7}, {%8,%9}, {%0,%1,%2,%3};"
        : "+f"(d[0]), "+f"(d[1]), "+f"(d[2]), "+f"(d[3])
        : "r"(a[0]), "r"(a[1]), "r"(a[2]), "r"(a[3]), "r"(b[0]), "r"(b[1]));
}
__device__ __forceinline__ void ldm4(uint32_t* r, uint32_t a) {
    asm volatile("ldmatrix.sync.aligned.m8n8.x4.shared.b16 {%0,%1,%2,%3}, [%4];"
        : "=r"(r[0]), "=r"(r[1]), "=r"(r[2]), "=r"(r[3]) : "r"(a));
}
__device__ __forceinline__ uint32_t pack2h(__half a, __half b) {
    return (uint32_t)__half_as_ushort(a) |
           ((uint32_t)__half_as_ushort(b) << 16);
}
__device__ __forceinline__ void split2h(float f, __half& h, __half& l) {
    h = __float2half(f);
    l = __float2half(f - __half2float(h));
}

// lane offsets (half elem units) for ldmatrix addressing
__device__ __forceinline__ int laneA_off(int lane) {
    return ((lane & 7) + ((lane >> 3) & 1) * 8) * LDT + ((lane >> 4) & 1) * 8;
}
__device__ __forceinline__ int laneB_off(int lane) {
    return ((lane & 7) + ((lane >> 4) & 1) * 8) * LDT + ((lane >> 3) & 1) * 8;
}

// 1-pass compute body: ah * bh
__device__ __forceinline__ void compute_ks1(float acc[4][4][4],
                                            uint32_t aHi, uint32_t bHi)
{
    uint32_t ah[4][4], bh[2][4];
    #pragma unroll
    for (int i = 0; i < 4; i++) ldm4(ah[i], aHi + i * (16 * LDT * 2));
    #pragma unroll
    for (int jp = 0; jp < 2; jp++) ldm4(bh[jp], bHi + jp * (16 * LDT * 2));
    #pragma unroll
    for (int i = 0; i < 4; i++) {
        mma16816(acc[i][0], ah[i], bh[0]);
        mma16816(acc[i][1], ah[i], bh[0] + 2);
        mma16816(acc[i][2], ah[i], bh[1]);
        mma16816(acc[i][3], ah[i], bh[1] + 2);
    }
}

// 2-pass compute body: (ah + al) * bh
__device__ __forceinline__ void compute_ks2(float acc[4][4][4],
                                            uint32_t aHi, uint32_t aLo,
                                            uint32_t bHi)
{
    uint32_t ah[4][4], al_[4][4], bh[2][4];
    #pragma unroll
    for (int i = 0; i < 4; i++) ldm4(ah[i], aHi + i * (16 * LDT * 2));
    #pragma unroll
    for (int jp = 0; jp < 2; jp++) ldm4(bh[jp], bHi + jp * (16 * LDT * 2));
    #pragma unroll
    for (int i = 0; i < 4; i++) {
        ldm4(al_[i], aLo + i * (16 * LDT * 2));
        mma16816(acc[i][0], ah[i], bh[0]);
        mma16816(acc[i][1], ah[i], bh[0] + 2);
        mma16816(acc[i][2], ah[i], bh[1]);
        mma16816(acc[i][3], ah[i], bh[1] + 2);
    }
    #pragma unroll
    for (int i = 0; i < 4; i++) {
        mma16816(acc[i][0], al_[i], bh[0]);
        mma16816(acc[i][1], al_[i], bh[0] + 2);
        mma16816(acc[i][2], al_[i], bh[1]);
        mma16816(acc[i][3], al_[i], bh[1] + 2);
    }
}

// ============== BIG kernel: 128x256, 512 thr, 3-stage =====================
// OUTMODE: 0 = f32, 1 = split hi/lo fp16, 2 = hi-only fp16
// PASSES:  1 = ah*bh ; 2 = (ah+al)*bh
#define BM2 128
#define BN2 256
#define NST2 3
#define Q_AH 0
#define Q_AL (128 * LDT)
#define Q_BH (256 * LDT)
#define STAGE_EL2 (512 * LDT)
#define STAGE_BY2 (STAGE_EL2 * 2)             // 40960 B
#define SMEM_BY2 (NST2 * STAGE_BY2)           // 122880 B

template<bool HASBIAS, int OUTMODE, int PASSES>
__global__ __launch_bounds__(512)
void gemm_big(const __half* __restrict__ Ah, const __half* __restrict__ Al,
              const __half* __restrict__ Bh,
              float* __restrict__ Cf,
              __half* __restrict__ Ch, __half* __restrict__ Cl,
              const float* __restrict__ bias,
              int K, int lda, int ldb, int ldc,
              size_t sA_, size_t sB_, size_t sC_)
{
    extern __shared__ __half smem[];
    const int tid  = threadIdx.x;
    const int warp = tid >> 5;
    const int lane = tid & 31;
    const int wm   = (warp >> 3) * 64;   // 2 warps in M
    const int wn   = (warp & 7) * 32;    // 8 warps in N
    const int tm   = blockIdx.y * BM2;
    const int tn   = blockIdx.x * BN2;

    const __half* Ahb = Ah + (size_t)blockIdx.z * sA_;
    const __half* Alb = (PASSES == 2) ? Al + (size_t)blockIdx.z * sA_ : nullptr;
    const __half* Bhb = Bh + (size_t)blockIdx.z * sB_;

    const int arow = tid >> 2, ag = (tid & 3) * 8;

    const __half* pAh  = Ahb + (size_t)(tm + arow) * lda + ag;
    const __half* pAl  = (PASSES == 2) ? Alb + (size_t)(tm + arow) * lda + ag : nullptr;
    const __half* pB1h = Bhb + (size_t)(tn + arow) * ldb + ag;
    const __half* pB2h = Bhb + (size_t)(tn + 128 + arow) * ldb + ag;

    const uint32_t sbase = smem_u32(smem);
    const uint32_t dA  = (arow * LDT + ag) * 2;
    const uint32_t dB2 = ((arow + 128) * LDT + ag) * 2;

    const int lA = laneA_off(lane);
    const int lB = laneB_off(lane);

    float acc[4][4][4];
    #pragma unroll
    for (int i = 0; i < 4; i++)
        #pragma unroll
        for (int j = 0; j < 4; j++)
            #pragma unroll
            for (int t = 0; t < 4; t++) acc[i][j][t] = 0.f;

    auto issue = [&](int c) {
        const uint32_t sb = sbase + (c % NST2) * STAGE_BY2;
        const int k0 = c * BK;
        cp16(sb + Q_AH * 2 + dA,  pAh + k0);
        if (PASSES == 2) cp16(sb + Q_AL * 2 + dA, pAl + k0);
        cp16(sb + Q_BH * 2 + dA,  pB1h + k0);
        cp16(sb + Q_BH * 2 + dB2, pB2h + k0);
    };

    const int nc = K / BK;
    issue(0);
    asm volatile("cp.async.commit_group;");
    issue(1);
    asm volatile("cp.async.commit_group;");

    for (int c = 0; c < nc; ++c) {
        asm volatile("cp.async.wait_group 1;");
        __syncthreads();
        if (c + 2 < nc) issue(c + 2);
        asm volatile("cp.async.commit_group;");

        const uint32_t stb = sbase + (c % NST2) * STAGE_BY2;
        const uint32_t aH0 = stb + Q_AH * 2 + (wm * LDT + lA) * 2;
        const uint32_t aL0 = stb + Q_AL * 2 + (wm * LDT + lA) * 2;
        const uint32_t bH0 = stb + Q_BH * 2 + (wn * LDT + lB) * 2;
        #pragma unroll
        for (int ks = 0; ks < 2; ++ks) {
            const uint32_t ko = ks * 32;   // 16 halves = 32 bytes
            if (PASSES == 2) compute_ks2(acc, aH0 + ko, aL0 + ko, bH0 + ko);
            else             compute_ks1(acc, aH0 + ko, bH0 + ko);
        }
    }

    // ---------------- epilogue ----------------
    #pragma unroll
    for (int i = 0; i < 4; i++) {
        const int r0 = tm + wm + i * 16 + (lane >> 2);
        float bv0 = 0.f, bv1 = 0.f;
        if (HASBIAS) { bv0 = bias[r0]; bv1 = bias[r0 + 8]; }
        #pragma unroll
        for (int j = 0; j < 4; j++) {
            const int cc = tn + wn + j * 8 + (lane & 3) * 2;
            float d0 = acc[i][j][0] + bv0, d1 = acc[i][j][1] + bv0;
            float d2 = acc[i][j][2] + bv1, d3 = acc[i][j][3] + bv1;
            if (OUTMODE == 0) {
                float* cfp = Cf + (size_t)blockIdx.z * sC_;
                *reinterpret_cast<float2*>(&cfp[(size_t)r0 * ldc + cc])       = make_float2(d0, d1);
                *reinterpret_cast<float2*>(&cfp[(size_t)(r0 + 8) * ldc + cc]) = make_float2(d2, d3);
            } else if (OUTMODE == 1) {
                __half* chp = Ch + (size_t)blockIdx.z * sC_;
                __half* clp = Cl + (size_t)blockIdx.z * sC_;
                __half h0, h1, h2, h3, l0, l1, l2, l3;
                split2h(d0, h0, l0); split2h(d1, h1, l1);
                split2h(d2, h2, l2); split2h(d3, h3, l3);
                *reinterpret_cast<uint32_t*>(&chp[(size_t)r0 * ldc + cc])       = pack2h(h0, h1);
                *reinterpret_cast<uint32_t*>(&clp[(size_t)r0 * ldc + cc])       = pack2h(l0, l1);
                *reinterpret_cast<uint32_t*>(&chp[(size_t)(r0 + 8) * ldc + cc]) = pack2h(h2, h3);
                *reinterpret_cast<uint32_t*>(&clp[(size_t)(r0 + 8) * ldc + cc]) = pack2h(l2, l3);
            } else {
                __half* chp = Ch + (size_t)blockIdx.z * sC_;
                *reinterpret_cast<uint32_t*>(&chp[(size_t)r0 * ldc + cc]) =
                    pack2h(__float2half(d0), __float2half(d1));
                *reinterpret_cast<uint32_t*>(&chp[(size_t)(r0 + 8) * ldc + cc]) =
                    pack2h(__float2half(d2), __float2half(d3));
            }
        }
    }
}

// ====== S kernel: 128x128, 256 thr, 2-stage, 2-pass, split-K ==============
// blockIdx.z = batch * KSPLIT + split ; each split covers K/KSPLIT
#define SP_AH 0
#define SP_AL (128 * LDT)
#define SP_BH (256 * LDT)
#define STAGE_ELS (384 * LDT)
#define STAGE_BYS (STAGE_ELS * 2)             // 30720 B
#define NSTS 2
#define SMEM_BYS (NSTS * STAGE_BYS)           // 61440 B

__global__ __launch_bounds__(256)
void gemm_s(const __half* __restrict__ Ah, const __half* __restrict__ Al,
            const __half* __restrict__ Bh,
            float* __restrict__ Cf,
            int K, int lda, int ldb, int ldc,
            size_t sA_, size_t sB_, size_t sC_)
{
    extern __shared__ __half smem[];
    const int tid  = threadIdx.x;
    const int warp = tid >> 5;
    const int lane = tid & 31;
    const int wm   = (warp >> 2) * 64;
    const int wn   = (warp & 3) * 32;
    const int tm   = blockIdx.y * 128;
    const int tn   = blockIdx.x * 128;
    const int batch = blockIdx.z / KSPLIT;
    const int split = blockIdx.z % KSPLIT;
    const int kper  = K / KSPLIT;
    const int kbase = split * kper;

    const __half* Ahb = Ah + (size_t)batch * sA_ + kbase;
    const __half* Alb = Al + (size_t)batch * sA_ + kbase;
    const __half* Bhb = Bh + (size_t)batch * sB_ + kbase;

    const int lrow = tid >> 1;
    const int lg   = (tid & 1) * 16;
    const __half* pAh = Ahb + (size_t)(tm + lrow) * lda + lg;
    const __half* pAl = Alb + (size_t)(tm + lrow) * lda + lg;
    const __half* pBh = Bhb + (size_t)(tn + lrow) * ldb + lg;
    const uint32_t sbase = smem_u32(smem);
    const uint32_t doff  = (lrow * LDT + lg) * 2;

    const int lA = laneA_off(lane);
    const int lB = laneB_off(lane);

    float acc[4][4][4];
    #pragma unroll
    for (int i = 0; i < 4; i++)
        #pragma unroll
        for (int j = 0; j < 4; j++)
            #pragma unroll
            for (int t = 0; t < 4; t++) acc[i][j][t] = 0.f;

    auto issue = [&](int c) {
        const uint32_t sb = sbase + (c & 1) * STAGE_BYS + doff;
        const int k0 = c * BK;
        cp16(sb + SP_AH * 2,      pAh + k0);
        cp16(sb + SP_AH * 2 + 16, pAh + k0 + 8);
        cp16(sb + SP_AL * 2,      pAl + k0);
        cp16(sb + SP_AL * 2 + 16, pAl + k0 + 8);
        cp16(sb + SP_BH * 2,      pBh + k0);
        cp16(sb + SP_BH * 2 + 16, pBh + k0 + 8);
    };

    const int nc = kper / BK;
    issue(0);
    asm volatile("cp.async.commit_group;");

    for (int c = 0; c < nc; ++c) {
        asm volatile("cp.async.wait_group 0;");
        __syncthreads();
        if (c + 1 < nc) issue(c + 1);
        asm volatile("cp.async.commit_group;");

        const uint32_t stb = sbase + (c & 1) * STAGE_BYS;
        const uint32_t aH0 = stb + SP_AH * 2 + (wm * LDT + lA) * 2;
        const uint32_t aL0 = stb + SP_AL * 2 + (wm * LDT + lA) * 2;
        const uint32_t bH0 = stb + SP_BH * 2 + (wn * LDT + lB) * 2;
        #pragma unroll
        for (int ks = 0; ks < 2; ++ks) {
            const uint32_t ko = ks * 32;
            compute_ks2(acc, aH0 + ko, aL0 + ko, bH0 + ko);
        }
    }

    // write partial: plane = split
    float* cfp = Cf + (size_t)split * B_ * C_ * C_ + (size_t)batch * sC_;
    #pragma unroll
    for (int i = 0; i < 4; i++) {
        const int r0 = tm + wm + i * 16 + (lane >> 2);
        #pragma unroll
        for (int j = 0; j < 4; j++) {
            const int cc = tn + wn + j * 8 + (lane & 3) * 2;
            *reinterpret_cast<float2*>(&cfp[(size_t)r0 * ldc + cc]) =
                make_float2(acc[i][j][0], acc[i][j][1]);
            *reinterpret_cast<float2*>(&cfp[(size_t)(r0 + 8) * ldc + cc]) =
                make_float2(acc[i][j][2], acc[i][j][3]);
        }
    }
}

// ------------- transpose fp32 [R,Cc] -> fp16 hi [Cc,R] ---------------------
__global__ void transpose_hi(const float* __restrict__ in,
                             __half* __restrict__ oh,
                             int R, int Cc, size_t sIn, size_t sOut)
{
    __shared__ float t[32][33];
    const float* ip = in + (size_t)blockIdx.z * sIn;
    int r0 = blockIdx.y * 32, c0 = blockIdx.x * 32;
    #pragma unroll
    for (int j = threadIdx.y; j < 32; j += 8)
        t[j][threadIdx.x] = ip[(size_t)(r0 + j) * Cc + c0 + threadIdx.x];
    __syncthreads();
    #pragma unroll
    for (int j = threadIdx.y; j < 32; j += 8) {
        size_t idx = (size_t)blockIdx.z * sOut + (size_t)(c0 + j) * R + r0 + threadIdx.x;
        oh[idx] = __float2half(t[threadIdx.x][j]);
    }
}

// ------------- transpose two fp16 planes: [R,Cc] -> [Cc,R] -----------------
__global__ void transpose_h2(const __half* __restrict__ ih,
                             const __half* __restrict__ il,
                             __half* __restrict__ oh,
                             __half* __restrict__ ol,
                             int R, int Cc, size_t sIn, size_t sOut)
{
    __shared__ __half th[32][34], tl[32][34];
    const __half* ihp = ih + (size_t)blockIdx.z * sIn;
    const __half* ilp = il + (size_t)blockIdx.z * sIn;
    int r0 = blockIdx.y * 32, c0 = blockIdx.x * 32;
    #pragma unroll
    for (int j = threadIdx.y; j < 32; j += 8) {
        size_t s = (size_t)(r0 + j) * Cc + c0 + threadIdx.x;
        th[j][threadIdx.x] = ihp[s];
        tl[j][threadIdx.x] = ilp[s];
    }
    __syncthreads();
    #pragma unroll
    for (int j = threadIdx.y; j < 32; j += 8) {
        size_t d = (size_t)blockIdx.z * sOut + (size_t)(c0 + j) * R + r0 + threadIdx.x;
        oh[d] = th[threadIdx.x][j];
        ol[d] = tl[threadIdx.x][j];
    }
}

// ------------- elementwise casts ------------------------------------------
__global__ void split_w(const float* __restrict__ in,
                        __half* __restrict__ oh,
                        __half* __restrict__ ol, int n)
{
    int i = blockIdx.x * blockDim.x + threadIdx.x;
    if (i >= n) return;
    __half h, l;
    split2h(in[i], h, l);
    oh[i] = h;
    ol[i] = l;
}
__global__ void cast_hi(const float* __restrict__ in,
                        __half* __restrict__ oh, int n)
{
    int i = blockIdx.x * blockDim.x + threadIdx.x;
    if (i >= n) return;
    oh[i] = __float2half(in[i]);
}

// ----- softmax over summed split-K partials (fp32 in x4, fp16 hi out) ------
__global__ void softmax_hi(const float* __restrict__ Sp,
                           __half* __restrict__ oh, float scale)
{
    int warp = (blockIdx.x * blockDim.x + threadIdx.x) >> 5;
    int lane = threadIdx.x & 31;
    if (warp >= B_ * C_) return;
    const size_t rowoff = (size_t)warp * C_;
    const size_t plane  = (size_t)B_ * C_ * C_;

    float vals[C_ / 32];
    float m = -1e30f;
    #pragma unroll
    for (int t = 0; t < C_ / 32; t++) {
        size_t idx = rowoff + lane + t * 32;
        float v = Sp[idx];
        v += Sp[idx + plane];
        v += Sp[idx + 2 * plane];
        v += Sp[idx + 3 * plane];
        vals[t] = v * scale;
        m = fmaxf(m, vals[t]);
    }
    #pragma unroll
    for (int o = 16; o; o >>= 1) m = fmaxf(m, __shfl_xor_sync(0xffffffffu, m, o));
    float s = 0.f;
    #pragma unroll
    for (int t = 0; t < C_ / 32; t++) { vals[t] = __expf(vals[t] - m); s += vals[t]; }
    #pragma unroll
    for (int o = 16; o; o >>= 1) s += __shfl_xor_sync(0xffffffffu, s, o);
    float inv = 1.f / s;
    #pragma unroll
    for (int t = 0; t < C_ / 32; t++)
        oh[rowoff + lane + t * 32] = __float2half(vals[t] * inv);
}

// ---------------- launcher ----------------
extern "C" void kernel_launch(void* const* d_in, const int* in_sizes, int n_in,
                              void* d_out, int out_size)
{
    const float* x      = (const float*)d_in[0];
    const float* w_qkv  = (const float*)d_in[1];
    const float* b_qkv  = (const float*)d_in[2];
    const float* w_proj = (const float*)d_in[3];
    const float* b_proj = (const float*)d_in[4];
    float* out = (float*)d_out;

    __half *qh, *ql, *xTh, *vTh, *vTl, *ah, *wqh, *wph, *wpl;
    float *Sp;
    cudaGetSymbolAddress((void**)&qh,  g_qh);
    cudaGetSymbolAddress((void**)&ql,  g_ql);
    cudaGetSymbolAddress((void**)&xTh, g_xTh);
    cudaGetSymbolAddress((void**)&vTh, g_vTh);
    cudaGetSymbolAddress((void**)&vTl, g_vTl);
    cudaGetSymbolAddress((void**)&Sp,  g_Sp);
    cudaGetSymbolAddress((void**)&ah,  g_ah);
    cudaGetSymbolAddress((void**)&wqh, g_wqh);
    cudaGetSymbolAddress((void**)&wph, g_wph);
    cudaGetSymbolAddress((void**)&wpl, g_wpl);

    cudaFuncSetAttribute(gemm_big<true,  1, 1>, cudaFuncAttributeMaxDynamicSharedMemorySize, SMEM_BY2);
    cudaFuncSetAttribute(gemm_big<false, 2, 2>, cudaFuncAttributeMaxDynamicSharedMemorySize, SMEM_BY2);
    cudaFuncSetAttribute(gemm_big<true,  0, 2>, cudaFuncAttributeMaxDynamicSharedMemorySize, SMEM_BY2);
    cudaFuncSetAttribute(gemm_s, cudaFuncAttributeMaxDynamicSharedMemorySize, SMEM_BYS);

    const float scale = 1.0f / sqrtf((float)C_);
    dim3 tblk(32, 8);

    // 0) weights: qkv hi only (1-pass GEMM), proj hi/lo (2-pass GEMM)
    cast_hi<<<(O3 * C_ + 255) / 256, 256>>>(w_qkv, wqh, O3 * C_);
    split_w<<<(C_ * C_ + 255) / 256, 256>>>(w_proj, wph, wpl, C_ * C_);

    // 1) xT hi: x[b,c,n] -> [b,n,c]
    transpose_hi<<<dim3(N_ / 32, C_ / 32, B_), tblk>>>(
        x, xTh, C_, N_, (size_t)C_ * N_, (size_t)N_ * C_);

    // 2) qkv = w_qkv @ xT^T + b  (1-pass) -> fp16 hi/lo
    gemm_big<true, 1, 1><<<dim3(N_ / BN2, O3 / BM2, B_), 512, SMEM_BY2>>>(
        wqh, nullptr, xTh, nullptr, qh, ql, b_qkv,
        C_, C_, C_, N_,
        0, (size_t)N_ * C_, (size_t)O3 * N_);

    // 3) vT hi/lo: v[b,d,n] -> [b,n,d]
    transpose_h2<<<dim3(N_ / 32, C_ / 32, B_), tblk>>>(
        qh + (size_t)2 * C_ * N_, ql + (size_t)2 * C_ * N_, vTh, vTl,
        C_, N_, (size_t)O3 * N_, (size_t)N_ * C_);

    // 4) S partials = q @ k^T (2-pass, split-K x4) -> fp32
    gemm_s<<<dim3(C_ / 128, C_ / 128, B_ * KSPLIT), 256, SMEM_BYS>>>(
        qh, ql, qh + (size_t)C_ * N_, Sp,
        N_, N_, N_, C_,
        (size_t)O3 * N_, (size_t)O3 * N_, (size_t)C_ * C_);

    // 5) softmax over summed partials -> attn hi
    softmax_hi<<<(B_ * C_ * 32 + 255) / 256, 256>>>(Sp, ah, scale);

    // 6) o1T[b,n,c] = vT[b,n,:] @ attn[b,c,:]  (2-pass) -> hi only (reuse xTh)
    gemm_big<false, 2, 2><<<dim3(C_ / BN2, N_ / BM2, B_), 512, SMEM_BY2>>>(
        vTh, vTl, ah, nullptr, xTh, nullptr, nullptr,
        C_, C_, C_, C_,
        (size_t)N_ * C_, (size_t)C_ * C_, (size_t)N_ * C_);

    // 7) out = w_proj @ o1T^T + b  (2-pass) -> fp32
    gemm_big<true, 0, 2><<<dim3(N_ / BN2, C_ / BM2, B_), 512, SMEM_BY2>>>(
        wph, wpl, xTh, out, nullptr, nullptr, b_proj,
        C_, C_, C_, N_,
        0, (size_t)N_ * C_, (size_t)C_ * N_);
}

// round 14
// speedup vs baseline: 1.6064x; 1.1711x over previous
#include <cuda_runtime.h>
#include <cuda_fp16.h>
#include <math.h>
#include <stdint.h>

// ---------------- problem constants ----------------
constexpr int B_ = 8, C_ = 512, H_ = 96, W_ = 96;
constexpr int N_ = H_ * W_;    // 9216
constexpr int O3 = 3 * C_;     // 1536
constexpr int KSPLIT = 4;      // split-K factor for the S GEMM

// ---------------- scratch: fp16 planes ----------------
__device__ __align__(256) __half g_qh [(size_t)B_ * O3 * N_];   // qkv hi
__device__ __align__(256) __half g_ql [(size_t)B_ * O3 * N_];   // qkv lo
__device__ __align__(256) __half g_xTh[(size_t)B_ * N_ * C_];   // xT hi
__device__ __align__(256) __half g_vTh[(size_t)B_ * N_ * C_];   // vT hi
__device__ __align__(256) float  g_Sp [(size_t)KSPLIT * B_ * C_ * C_];  // split-K partials
__device__ __align__(256) __half g_ah [(size_t)B_ * C_ * C_];   // attn hi
__device__ __align__(256) __half g_aT [(size_t)B_ * C_ * C_];   // attn^T hi
__device__ __align__(256) __half g_Mh [(size_t)B_ * C_ * C_];   // M = wp@attn, hi
__device__ __align__(256) __half g_Ml [(size_t)B_ * C_ * C_];   // M lo
__device__ __align__(256) __half g_wqh[(size_t)O3 * C_];
__device__ __align__(256) __half g_wph[(size_t)C_ * C_];
__device__ __align__(256) __half g_wpl[(size_t)C_ * C_];

// ---------------- common helpers ----------------
#define BK 32
#define LDT 40   // smem row stride in halves (BK + 8 pad)

__device__ __forceinline__ uint32_t smem_u32(const void* p) {
    uint32_t a;
    asm("{ .reg .u64 t; cvta.to.shared.u64 t, %1; cvt.u32.u64 %0, t; }"
        : "=r"(a) : "l"(p));
    return a;
}
__device__ __forceinline__ void cp16(uint32_t dst, const void* src) {
    asm volatile("cp.async.cg.shared.global [%0], [%1], 16;"
                 :: "r"(dst), "l"(src));
}
__device__ __forceinline__ void mma16816(float* d, const uint32_t* a,
                                         const uint32_t* b) {
    asm volatile(
        "mma.sync.aligned.m16n8k16.row.col.f32.f16.f16.f32 "
        "{%0,%1,%2,%3}, {%4,%5,%6,%7}, {%8,%9}, {%0,%1,%2,%3};"
        : "+f"(d[0]), "+f"(d[1]), "+f"(d[2]), "+f"(d[3])
        : "r"(a[0]), "r"(a[1]), "r"(a[2]), "r"(a[3]), "r"(b[0]), "r"(b[1]));
}
__device__ __forceinline__ void ldm4(uint32_t* r, uint32_t a) {
    asm volatile("ldmatrix.sync.aligned.m8n8.x4.shared.b16 {%0,%1,%2,%3}, [%4];"
        : "=r"(r[0]), "=r"(r[1]), "=r"(r[2]), "=r"(r[3]) : "r"(a));
}
__device__ __forceinline__ uint32_t pack2h(__half a, __half b) {
    return (uint32_t)__half_as_ushort(a) |
           ((uint32_t)__half_as_ushort(b) << 16);
}
__device__ __forceinline__ void split2h(float f, __half& h, __half& l) {
    h = __float2half(f);
    l = __float2half(f - __half2float(h));
}

// lane offsets (half elem units) for ldmatrix addressing
__device__ __forceinline__ int laneA_off(int lane) {
    return ((lane & 7) + ((lane >> 3) & 1) * 8) * LDT + ((lane >> 4) & 1) * 8;
}
__device__ __forceinline__ int laneB_off(int lane) {
    return ((lane & 7) + ((lane >> 4) & 1) * 8) * LDT + ((lane >> 3) & 1) * 8;
}

// 1-pass compute body: ah * bh
__device__ __forceinline__ void compute_ks1(float acc[4][4][4],
                                            uint32_t aHi, uint32_t bHi)
{
    uint32_t ah[4][4], bh[2][4];
    #pragma unroll
    for (int i = 0; i < 4; i++) ldm4(ah[i], aHi + i * (16 * LDT * 2));
    #pragma unroll
    for (int jp = 0; jp < 2; jp++) ldm4(bh[jp], bHi + jp * (16 * LDT * 2));
    #pragma unroll
    for (int i = 0; i < 4; i++) {
        mma16816(acc[i][0], ah[i], bh[0]);
        mma16816(acc[i][1], ah[i], bh[0] + 2);
        mma16816(acc[i][2], ah[i], bh[1]);
        mma16816(acc[i][3], ah[i], bh[1] + 2);
    }
}

// 2-pass compute body: (ah + al) * bh
__device__ __forceinline__ void compute_ks2(float acc[4][4][4],
                                            uint32_t aHi, uint32_t aLo,
                                            uint32_t bHi)
{
    uint32_t ah[4][4], al_[4][4], bh[2][4];
    #pragma unroll
    for (int i = 0; i < 4; i++) ldm4(ah[i], aHi + i * (16 * LDT * 2));
    #pragma unroll
    for (int jp = 0; jp < 2; jp++) ldm4(bh[jp], bHi + jp * (16 * LDT * 2));
    #pragma unroll
    for (int i = 0; i < 4; i++) {
        ldm4(al_[i], aLo + i * (16 * LDT * 2));
        mma16816(acc[i][0], ah[i], bh[0]);
        mma16816(acc[i][1], ah[i], bh[0] + 2);
        mma16816(acc[i][2], ah[i], bh[1]);
        mma16816(acc[i][3], ah[i], bh[1] + 2);
    }
    #pragma unroll
    for (int i = 0; i < 4; i++) {
        mma16816(acc[i][0], al_[i], bh[0]);
        mma16816(acc[i][1], al_[i], bh[0] + 2);
        mma16816(acc[i][2], al_[i], bh[1]);
        mma16816(acc[i][3], al_[i], bh[1] + 2);
    }
}

// ============== BIG kernel: 128x256, 512 thr, 3-stage =====================
// OUTMODE: 0 = f32, 1 = split hi/lo fp16, 2 = hi-only fp16
// PASSES:  1 = ah*bh ; 2 = (ah+al)*bh
#define BM2 128
#define BN2 256
#define NST2 3
#define Q_AH 0
#define Q_AL (128 * LDT)
#define Q_BH (256 * LDT)
#define STAGE_EL2 (512 * LDT)
#define STAGE_BY2 (STAGE_EL2 * 2)             // 40960 B
#define SMEM_BY2 (NST2 * STAGE_BY2)           // 122880 B

template<bool HASBIAS, int OUTMODE, int PASSES>
__global__ __launch_bounds__(512)
void gemm_big(const __half* __restrict__ Ah, const __half* __restrict__ Al,
              const __half* __restrict__ Bh,
              float* __restrict__ Cf,
              __half* __restrict__ Ch, __half* __restrict__ Cl,
              const float* __restrict__ bias,
              int K, int lda, int ldb, int ldc,
              size_t sA_, size_t sB_, size_t sC_)
{
    extern __shared__ __half smem[];
    const int tid  = threadIdx.x;
    const int warp = tid >> 5;
    const int lane = tid & 31;
    const int wm   = (warp >> 3) * 64;   // 2 warps in M
    const int wn   = (warp & 7) * 32;    // 8 warps in N
    const int tm   = blockIdx.y * BM2;
    const int tn   = blockIdx.x * BN2;

    const __half* Ahb = Ah + (size_t)blockIdx.z * sA_;
    const __half* Alb = (PASSES == 2) ? Al + (size_t)blockIdx.z * sA_ : nullptr;
    const __half* Bhb = Bh + (size_t)blockIdx.z * sB_;

    const int arow = tid >> 2, ag = (tid & 3) * 8;

    const __half* pAh  = Ahb + (size_t)(tm + arow) * lda + ag;
    const __half* pAl  = (PASSES == 2) ? Alb + (size_t)(tm + arow) * lda + ag : nullptr;
    const __half* pB1h = Bhb + (size_t)(tn + arow) * ldb + ag;
    const __half* pB2h = Bhb + (size_t)(tn + 128 + arow) * ldb + ag;

    const uint32_t sbase = smem_u32(smem);
    const uint32_t dA  = (arow * LDT + ag) * 2;
    const uint32_t dB2 = ((arow + 128) * LDT + ag) * 2;

    const int lA = laneA_off(lane);
    const int lB = laneB_off(lane);

    float acc[4][4][4];
    #pragma unroll
    for (int i = 0; i < 4; i++)
        #pragma unroll
        for (int j = 0; j < 4; j++)
            #pragma unroll
            for (int t = 0; t < 4; t++) acc[i][j][t] = 0.f;

    auto issue = [&](int c) {
        const uint32_t sb = sbase + (c % NST2) * STAGE_BY2;
        const int k0 = c * BK;
        cp16(sb + Q_AH * 2 + dA,  pAh + k0);
        if (PASSES == 2) cp16(sb + Q_AL * 2 + dA, pAl + k0);
        cp16(sb + Q_BH * 2 + dA,  pB1h + k0);
        cp16(sb + Q_BH * 2 + dB2, pB2h + k0);
    };

    const int nc = K / BK;
    issue(0);
    asm volatile("cp.async.commit_group;");
    issue(1);
    asm volatile("cp.async.commit_group;");

    for (int c = 0; c < nc; ++c) {
        asm volatile("cp.async.wait_group 1;");
        __syncthreads();
        if (c + 2 < nc) issue(c + 2);
        asm volatile("cp.async.commit_group;");

        const uint32_t stb = sbase + (c % NST2) * STAGE_BY2;
        const uint32_t aH0 = stb + Q_AH * 2 + (wm * LDT + lA) * 2;
        const uint32_t aL0 = stb + Q_AL * 2 + (wm * LDT + lA) * 2;
        const uint32_t bH0 = stb + Q_BH * 2 + (wn * LDT + lB) * 2;
        #pragma unroll
        for (int ks = 0; ks < 2; ++ks) {
            const uint32_t ko = ks * 32;   // 16 halves = 32 bytes
            if (PASSES == 2) compute_ks2(acc, aH0 + ko, aL0 + ko, bH0 + ko);
            else             compute_ks1(acc, aH0 + ko, bH0 + ko);
        }
    }

    // ---------------- epilogue ----------------
    #pragma unroll
    for (int i = 0; i < 4; i++) {
        const int r0 = tm + wm + i * 16 + (lane >> 2);
        float bv0 = 0.f, bv1 = 0.f;
        if (HASBIAS) { bv0 = bias[r0]; bv1 = bias[r0 + 8]; }
        #pragma unroll
        for (int j = 0; j < 4; j++) {
            const int cc = tn + wn + j * 8 + (lane & 3) * 2;
            float d0 = acc[i][j][0] + bv0, d1 = acc[i][j][1] + bv0;
            float d2 = acc[i][j][2] + bv1, d3 = acc[i][j][3] + bv1;
            if (OUTMODE == 0) {
                float* cfp = Cf + (size_t)blockIdx.z * sC_;
                *reinterpret_cast<float2*>(&cfp[(size_t)r0 * ldc + cc])       = make_float2(d0, d1);
                *reinterpret_cast<float2*>(&cfp[(size_t)(r0 + 8) * ldc + cc]) = make_float2(d2, d3);
            } else if (OUTMODE == 1) {
                __half* chp = Ch + (size_t)blockIdx.z * sC_;
                __half* clp = Cl + (size_t)blockIdx.z * sC_;
                __half h0, h1, h2, h3, l0, l1, l2, l3;
                split2h(d0, h0, l0); split2h(d1, h1, l1);
                split2h(d2, h2, l2); split2h(d3, h3, l3);
                *reinterpret_cast<uint32_t*>(&chp[(size_t)r0 * ldc + cc])       = pack2h(h0, h1);
                *reinterpret_cast<uint32_t*>(&clp[(size_t)r0 * ldc + cc])       = pack2h(l0, l1);
                *reinterpret_cast<uint32_t*>(&chp[(size_t)(r0 + 8) * ldc + cc]) = pack2h(h2, h3);
                *reinterpret_cast<uint32_t*>(&clp[(size_t)(r0 + 8) * ldc + cc]) = pack2h(l2, l3);
            } else {
                __half* chp = Ch + (size_t)blockIdx.z * sC_;
                *reinterpret_cast<uint32_t*>(&chp[(size_t)r0 * ldc + cc]) =
                    pack2h(__float2half(d0), __float2half(d1));
                *reinterpret_cast<uint32_t*>(&chp[(size_t)(r0 + 8) * ldc + cc]) =
                    pack2h(__float2half(d2), __float2half(d3));
            }
        }
    }
}

// ====== S kernel: 128x128, 256 thr, 2-stage, 2-pass, split-K ==============
#define SP_AH 0
#define SP_AL (128 * LDT)
#define SP_BH (256 * LDT)
#define STAGE_ELS (384 * LDT)
#define STAGE_BYS (STAGE_ELS * 2)             // 30720 B
#define NSTS 2
#define SMEM_BYS (NSTS * STAGE_BYS)           // 61440 B

__global__ __launch_bounds__(256)
void gemm_s(const __half* __restrict__ Ah, const __half* __restrict__ Al,
            const __half* __restrict__ Bh,
            float* __restrict__ Cf,
            int K, int lda, int ldb, int ldc,
            size_t sA_, size_t sB_, size_t sC_)
{
    extern __shared__ __half smem[];
    const int tid  = threadIdx.x;
    const int warp = tid >> 5;
    const int lane = tid & 31;
    const int wm   = (warp >> 2) * 64;
    const int wn   = (warp & 3) * 32;
    const int tm   = blockIdx.y * 128;
    const int tn   = blockIdx.x * 128;
    const int batch = blockIdx.z / KSPLIT;
    const int split = blockIdx.z % KSPLIT;
    const int kper  = K / KSPLIT;
    const int kbase = split * kper;

    const __half* Ahb = Ah + (size_t)batch * sA_ + kbase;
    const __half* Alb = Al + (size_t)batch * sA_ + kbase;
    const __half* Bhb = Bh + (size_t)batch * sB_ + kbase;

    const int lrow = tid >> 1;
    const int lg   = (tid & 1) * 16;
    const __half* pAh = Ahb + (size_t)(tm + lrow) * lda + lg;
    const __half* pAl = Alb + (size_t)(tm + lrow) * lda + lg;
    const __half* pBh = Bhb + (size_t)(tn + lrow) * ldb + lg;
    const uint32_t sbase = smem_u32(smem);
    const uint32_t doff  = (lrow * LDT + lg) * 2;

    const int lA = laneA_off(lane);
    const int lB = laneB_off(lane);

    float acc[4][4][4];
    #pragma unroll
    for (int i = 0; i < 4; i++)
        #pragma unroll
        for (int j = 0; j < 4; j++)
            #pragma unroll
            for (int t = 0; t < 4; t++) acc[i][j][t] = 0.f;

    auto issue = [&](int c) {
        const uint32_t sb = sbase + (c & 1) * STAGE_BYS + doff;
        const int k0 = c * BK;
        cp16(sb + SP_AH * 2,      pAh + k0);
        cp16(sb + SP_AH * 2 + 16, pAh + k0 + 8);
        cp16(sb + SP_AL * 2,      pAl + k0);
        cp16(sb + SP_AL * 2 + 16, pAl + k0 + 8);
        cp16(sb + SP_BH * 2,      pBh + k0);
        cp16(sb + SP_BH * 2 + 16, pBh + k0 + 8);
    };

    const int nc = kper / BK;
    issue(0);
    asm volatile("cp.async.commit_group;");

    for (int c = 0; c < nc; ++c) {
        asm volatile("cp.async.wait_group 0;");
        __syncthreads();
        if (c + 1 < nc) issue(c + 1);
        asm volatile("cp.async.commit_group;");

        const uint32_t stb = sbase + (c & 1) * STAGE_BYS;
        const uint32_t aH0 = stb + SP_AH * 2 + (wm * LDT + lA) * 2;
        const uint32_t aL0 = stb + SP_AL * 2 + (wm * LDT + lA) * 2;
        const uint32_t bH0 = stb + SP_BH * 2 + (wn * LDT + lB) * 2;
        #pragma unroll
        for (int ks = 0; ks < 2; ++ks) {
            const uint32_t ko = ks * 32;
            compute_ks2(acc, aH0 + ko, aL0 + ko, bH0 + ko);
        }
    }

    float* cfp = Cf + (size_t)split * B_ * C_ * C_ + (size_t)batch * sC_;
    #pragma unroll
    for (int i = 0; i < 4; i++) {
        const int r0 = tm + wm + i * 16 + (lane >> 2);
        #pragma unroll
        for (int j = 0; j < 4; j++) {
            const int cc = tn + wn + j * 8 + (lane & 3) * 2;
            *reinterpret_cast<float2*>(&cfp[(size_t)r0 * ldc + cc]) =
                make_float2(acc[i][j][0], acc[i][j][1]);
            *reinterpret_cast<float2*>(&cfp[(size_t)(r0 + 8) * ldc + cc]) =
                make_float2(acc[i][j][2], acc[i][j][3]);
        }
    }
}

// ------------- transpose fp32 [R,Cc] -> fp16 hi [Cc,R] ---------------------
__global__ void transpose_hi(const float* __restrict__ in,
                             __half* __restrict__ oh,
                             int R, int Cc, size_t sIn, size_t sOut)
{
    __shared__ float t[32][33];
    const float* ip = in + (size_t)blockIdx.z * sIn;
    int r0 = blockIdx.y * 32, c0 = blockIdx.x * 32;
    #pragma unroll
    for (int j = threadIdx.y; j < 32; j += 8)
        t[j][threadIdx.x] = ip[(size_t)(r0 + j) * Cc + c0 + threadIdx.x];
    __syncthreads();
    #pragma unroll
    for (int j = threadIdx.y; j < 32; j += 8) {
        size_t idx = (size_t)blockIdx.z * sOut + (size_t)(c0 + j) * R + r0 + threadIdx.x;
        oh[idx] = __float2half(t[threadIdx.x][j]);
    }
}

// ------------- transpose one fp16 plane: [R,Cc] -> [Cc,R] ------------------
__global__ void transpose_h1(const __half* __restrict__ ih,
                             __half* __restrict__ oh,
                             int R, int Cc, size_t sIn, size_t sOut)
{
    __shared__ __half t[32][34];
    const __half* ip = ih + (size_t)blockIdx.z * sIn;
    int r0 = blockIdx.y * 32, c0 = blockIdx.x * 32;
    #pragma unroll
    for (int j = threadIdx.y; j < 32; j += 8)
        t[j][threadIdx.x] = ip[(size_t)(r0 + j) * Cc + c0 + threadIdx.x];
    __syncthreads();
    #pragma unroll
    for (int j = threadIdx.y; j < 32; j += 8) {
        size_t d = (size_t)blockIdx.z * sOut + (size_t)(c0 + j) * R + r0 + threadIdx.x;
        oh[d] = t[threadIdx.x][j];
    }
}

// ------------- elementwise casts ------------------------------------------
__global__ void split_w(const float* __restrict__ in,
                        __half* __restrict__ oh,
                        __half* __restrict__ ol, int n)
{
    int i = blockIdx.x * blockDim.x + threadIdx.x;
    if (i >= n) return;
    __half h, l;
    split2h(in[i], h, l);
    oh[i] = h;
    ol[i] = l;
}
__global__ void cast_hi(const float* __restrict__ in,
                        __half* __restrict__ oh, int n)
{
    int i = blockIdx.x * blockDim.x + threadIdx.x;
    if (i >= n) return;
    oh[i] = __float2half(in[i]);
}

// ----- softmax over summed split-K partials (fp32 in x4, fp16 hi out) ------
__global__ void softmax_hi(const float* __restrict__ Sp,
                           __half* __restrict__ oh, float scale)
{
    int warp = (blockIdx.x * blockDim.x + threadIdx.x) >> 5;
    int lane = threadIdx.x & 31;
    if (warp >= B_ * C_) return;
    const size_t rowoff = (size_t)warp * C_;
    const size_t plane  = (size_t)B_ * C_ * C_;

    float vals[C_ / 32];
    float m = -1e30f;
    #pragma unroll
    for (int t = 0; t < C_ / 32; t++) {
        size_t idx = rowoff + lane + t * 32;
        float v = Sp[idx];
        v += Sp[idx + plane];
        v += Sp[idx + 2 * plane];
        v += Sp[idx + 3 * plane];
        vals[t] = v * scale;
        m = fmaxf(m, vals[t]);
    }
    #pragma unroll
    for (int o = 16; o; o >>= 1) m = fmaxf(m, __shfl_xor_sync(0xffffffffu, m, o));
    float s = 0.f;
    #pragma unroll
    for (int t = 0; t < C_ / 32; t++) { vals[t] = __expf(vals[t] - m); s += vals[t]; }
    #pragma unroll
    for (int o = 16; o; o >>= 1) s += __shfl_xor_sync(0xffffffffu, s, o);
    float inv = 1.f / s;
    #pragma unroll
    for (int t = 0; t < C_ / 32; t++)
        oh[rowoff + lane + t * 32] = __float2half(vals[t] * inv);
}

// ---------------- launcher ----------------
extern "C" void kernel_launch(void* const* d_in, const int* in_sizes, int n_in,
                              void* d_out, int out_size)
{
    const float* x      = (const float*)d_in[0];
    const float* w_qkv  = (const float*)d_in[1];
    const float* b_qkv  = (const float*)d_in[2];
    const float* w_proj = (const float*)d_in[3];
    const float* b_proj = (const float*)d_in[4];
    float* out = (float*)d_out;

    __half *qh, *ql, *xTh, *vTh, *ah, *aT, *Mh, *Ml, *wqh, *wph, *wpl;
    float *Sp;
    cudaGetSymbolAddress((void**)&qh,  g_qh);
    cudaGetSymbolAddress((void**)&ql,  g_ql);
    cudaGetSymbolAddress((void**)&xTh, g_xTh);
    cudaGetSymbolAddress((void**)&vTh, g_vTh);
    cudaGetSymbolAddress((void**)&Sp,  g_Sp);
    cudaGetSymbolAddress((void**)&ah,  g_ah);
    cudaGetSymbolAddress((void**)&aT,  g_aT);
    cudaGetSymbolAddress((void**)&Mh,  g_Mh);
    cudaGetSymbolAddress((void**)&Ml,  g_Ml);
    cudaGetSymbolAddress((void**)&wqh, g_wqh);
    cudaGetSymbolAddress((void**)&wph, g_wph);
    cudaGetSymbolAddress((void**)&wpl, g_wpl);

    cudaFuncSetAttribute(gemm_big<true,  1, 1>, cudaFuncAttributeMaxDynamicSharedMemorySize, SMEM_BY2);
    cudaFuncSetAttribute(gemm_big<false, 1, 2>, cudaFuncAttributeMaxDynamicSharedMemorySize, SMEM_BY2);
    cudaFuncSetAttribute(gemm_big<true,  0, 2>, cudaFuncAttributeMaxDynamicSharedMemorySize, SMEM_BY2);
    cudaFuncSetAttribute(gemm_s, cudaFuncAttributeMaxDynamicSharedMemorySize, SMEM_BYS);

    const float scale = 1.0f / sqrtf((float)C_);
    dim3 tblk(32, 8);

    // 0) weights: qkv hi only (1-pass GEMM), proj hi/lo (2-pass GEMM)
    cast_hi<<<(O3 * C_ + 255) / 256, 256>>>(w_qkv, wqh, O3 * C_);
    split_w<<<(C_ * C_ + 255) / 256, 256>>>(w_proj, wph, wpl, C_ * C_);

    // 1) xT hi: x[b,c,n] -> [b,n,c]
    transpose_hi<<<dim3(N_ / 32, C_ / 32, B_), tblk>>>(
        x, xTh, C_, N_, (size_t)C_ * N_, (size_t)N_ * C_);

    // 2) qkv = w_qkv @ xT^T + b  (1-pass) -> fp16 hi/lo
    gemm_big<true, 1, 1><<<dim3(N_ / BN2, O3 / BM2, B_), 512, SMEM_BY2>>>(
        wqh, nullptr, xTh, nullptr, qh, ql, b_qkv,
        C_, C_, C_, N_,
        0, (size_t)N_ * C_, (size_t)O3 * N_);

    // 3) vT hi: v[b,d,n] -> [b,n,d]  (lo plane of v is dead in the new path)
    transpose_h1<<<dim3(N_ / 32, C_ / 32, B_), tblk>>>(
        qh + (size_t)2 * C_ * N_, vTh,
        C_, N_, (size_t)O3 * N_, (size_t)N_ * C_);

    // 4) S partials = q @ k^T (2-pass, split-K x4) -> fp32
    gemm_s<<<dim3(C_ / 128, C_ / 128, B_ * KSPLIT), 256, SMEM_BYS>>>(
        qh, ql, qh + (size_t)C_ * N_, Sp,
        N_, N_, N_, C_,
        (size_t)O3 * N_, (size_t)O3 * N_, (size_t)C_ * C_);

    // 5) softmax over summed partials -> attn hi
    softmax_hi<<<(B_ * C_ * 32 + 255) / 256, 256>>>(Sp, ah, scale);

    // 5b) attn^T: [c,d] -> [d,c]
    transpose_h1<<<dim3(C_ / 32, C_ / 32, B_), tblk>>>(
        ah, aT, C_, C_, (size_t)C_ * C_, (size_t)C_ * C_);

    // 6) M[b,o,d] = sum_c wp[o,c] * attn[b,c,d]  (2-pass) -> fp16 hi/lo
    //    D[o,d] = sum_c wp[o,c] * aT[d,c]
    gemm_big<false, 1, 2><<<dim3(C_ / BN2, C_ / BM2, B_), 512, SMEM_BY2>>>(
        wph, wpl, aT, nullptr, Mh, Ml, nullptr,
        C_, C_, C_, C_,
        0, (size_t)C_ * C_, (size_t)C_ * C_);

    // 7) out[b,o,n] = sum_d M[b,o,d] * vT[b,n,d] + b_proj  (2-pass) -> fp32
    gemm_big<true, 0, 2><<<dim3(N_ / BN2, C_ / BM2, B_), 512, SMEM_BY2>>>(
        Mh, Ml, vTh, out, nullptr, nullptr, b_proj,
        C_, C_, C_, N_,
        (size_t)C_ * C_, (size_t)N_ * C_, (size_t)C_ * N_);
}

// round 16
// speedup vs baseline: 1.7029x; 1.0601x over previous
#include <cuda_runtime.h>
#include <cuda_fp16.h>
#include <math.h>
#include <stdint.h>

// ---------------- problem constants ----------------
constexpr int B_ = 8, C_ = 512, H_ = 96, W_ = 96;
constexpr int N_ = H_ * W_;    // 9216
constexpr int O3 = 3 * C_;     // 1536
constexpr int KSPLIT = 4;      // split-K factor for the S GEMM

// ---------------- scratch: fp16 planes ----------------
__device__ __align__(256) __half g_qh [(size_t)B_ * O3 * N_];   // qkv hi
__device__ __align__(256) __half g_ql [(size_t)B_ * O3 * N_];   // qkv lo (q rows only valid)
__device__ __align__(256) __half g_xTh[(size_t)B_ * N_ * C_];   // xT hi
__device__ __align__(256) __half g_vTh[(size_t)B_ * N_ * C_];   // vT hi
__device__ __align__(256) float  g_Sp [(size_t)KSPLIT * B_ * C_ * C_];  // split-K partials
__device__ __align__(256) __half g_ah [(size_t)B_ * C_ * C_];   // attn hi
__device__ __align__(256) __half g_aT [(size_t)B_ * C_ * C_];   // attn^T hi
__device__ __align__(256) __half g_Mh [(size_t)B_ * C_ * C_];   // M = wp@attn, hi
__device__ __align__(256) __half g_Ml [(size_t)B_ * C_ * C_];   // M lo
__device__ __align__(256) __half g_wqh[(size_t)O3 * C_];
__device__ __align__(256) __half g_wph[(size_t)C_ * C_];
__device__ __align__(256) __half g_wpl[(size_t)C_ * C_];

// ---------------- common helpers ----------------
#define BK 32
#define LDT 40   // smem row stride in halves (BK + 8 pad)

__device__ __forceinline__ uint32_t smem_u32(const void* p) {
    uint32_t a;
    asm("{ .reg .u64 t; cvta.to.shared.u64 t, %1; cvt.u32.u64 %0, t; }"
        : "=r"(a) : "l"(p));
    return a;
}
__device__ __forceinline__ void cp16(uint32_t dst, const void* src) {
    asm volatile("cp.async.cg.shared.global [%0], [%1], 16;"
                 :: "r"(dst), "l"(src));
}
__device__ __forceinline__ void mma16816(float* d, const uint32_t* a,
                                         const uint32_t* b) {
    asm volatile(
        "mma.sync.aligned.m16n8k16.row.col.f32.f16.f16.f32 "
        "{%0,%1,%2,%3}, {%4,%5,%6,%7}, {%8,%9}, {%0,%1,%2,%3};"
        : "+f"(d[0]), "+f"(d[1]), "+f"(d[2]), "+f"(d[3])
        : "r"(a[0]), "r"(a[1]), "r"(a[2]), "r"(a[3]), "r"(b[0]), "r"(b[1]));
}
__device__ __forceinline__ void ldm4(uint32_t* r, uint32_t a) {
    asm volatile("ldmatrix.sync.aligned.m8n8.x4.shared.b16 {%0,%1,%2,%3}, [%4];"
        : "=r"(r[0]), "=r"(r[1]), "=r"(r[2]), "=r"(r[3]) : "r"(a));
}
__device__ __forceinline__ uint32_t pack2h(__half a, __half b) {
    return (uint32_t)__half_as_ushort(a) |
           ((uint32_t)__half_as_ushort(b) << 16);
}
__device__ __forceinline__ void split2h(float f, __half& h, __half& l) {
    h = __float2half(f);
    l = __float2half(f - __half2float(h));
}

// lane offsets (half elem units) for ldmatrix addressing
__device__ __forceinline__ int laneA_off(int lane) {
    return ((lane & 7) + ((lane >> 3) & 1) * 8) * LDT + ((lane >> 4) & 1) * 8;
}
__device__ __forceinline__ int laneB_off(int lane) {
    return ((lane & 7) + ((lane >> 4) & 1) * 8) * LDT + ((lane >> 3) & 1) * 8;
}

// 1-pass compute body: ah * bh
__device__ __forceinline__ void compute_ks1(float acc[4][4][4],
                                            uint32_t aHi, uint32_t bHi)
{
    uint32_t ah[4][4], bh[2][4];
    #pragma unroll
    for (int i = 0; i < 4; i++) ldm4(ah[i], aHi + i * (16 * LDT * 2));
    #pragma unroll
    for (int jp = 0; jp < 2; jp++) ldm4(bh[jp], bHi + jp * (16 * LDT * 2));
    #pragma unroll
    for (int i = 0; i < 4; i++) {
        mma16816(acc[i][0], ah[i], bh[0]);
        mma16816(acc[i][1], ah[i], bh[0] + 2);
        mma16816(acc[i][2], ah[i], bh[1]);
        mma16816(acc[i][3], ah[i], bh[1] + 2);
    }
}

// 2-pass compute body: (ah + al) * bh
__device__ __forceinline__ void compute_ks2(float acc[4][4][4],
                                            uint32_t aHi, uint32_t aLo,
                                            uint32_t bHi)
{
    uint32_t ah[4][4], al_[4][4], bh[2][4];
    #pragma unroll
    for (int i = 0; i < 4; i++) ldm4(ah[i], aHi + i * (16 * LDT * 2));
    #pragma unroll
    for (int jp = 0; jp < 2; jp++) ldm4(bh[jp], bHi + jp * (16 * LDT * 2));
    #pragma unroll
    for (int i = 0; i < 4; i++) {
        ldm4(al_[i], aLo + i * (16 * LDT * 2));
        mma16816(acc[i][0], ah[i], bh[0]);
        mma16816(acc[i][1], ah[i], bh[0] + 2);
        mma16816(acc[i][2], ah[i], bh[1]);
        mma16816(acc[i][3], ah[i], bh[1] + 2);
    }
    #pragma unroll
    for (int i = 0; i < 4; i++) {
        mma16816(acc[i][0], al_[i], bh[0]);
        mma16816(acc[i][1], al_[i], bh[0] + 2);
        mma16816(acc[i][2], al_[i], bh[1]);
        mma16816(acc[i][3], al_[i], bh[1] + 2);
    }
}

// ============== QKV kernel: 128x256, 512 thr, A preloaded in smem ==========
// A = w_qkv (K=512 fixed). A slabs: 16 chunks x (128 rows x LDT halves).
// B (xT) streamed with 3-stage pipeline (prefetch depth 2 — stage-safe).
// Lo output gated to q rows (blockIdx.y < 4).
#define QKV_NC 16                              // 512 / BK
#define ASLAB_EL (128 * LDT)                   // 5120 halves per slab
#define ASLAB_BY (ASLAB_EL * 2)                // 10240 B
#define A_BYTES (QKV_NC * ASLAB_BY)            // 163840 B
#define QB_STAGE_EL (256 * LDT)
#define QB_STAGE_BY (QB_STAGE_EL * 2)          // 20480 B
#define QB_NST 3
#define SMEM_QKV (A_BYTES + QB_NST * QB_STAGE_BY)   // 225280 B

__global__ __launch_bounds__(512)
void gemm_qkv(const __half* __restrict__ Ahg, const __half* __restrict__ Bhg,
              __half* __restrict__ Ch, __half* __restrict__ Cl,
              const float* __restrict__ bias)
{
    extern __shared__ __half smem[];
    const int tid  = threadIdx.x;
    const int warp = tid >> 5;
    const int lane = tid & 31;
    const int wm   = (warp >> 3) * 64;
    const int wn   = (warp & 7) * 32;
    const int tm   = blockIdx.y * 128;
    const int tn   = blockIdx.x * 256;
    const bool wantLo = (blockIdx.y < 4);      // only q rows need the lo plane

    const __half* Bb = Bhg + (size_t)blockIdx.z * N_ * C_;

    const int ar = tid >> 2, ag = (tid & 3) * 8;
    const __half* pB1 = Bb + (size_t)(tn + ar) * C_ + ag;
    const __half* pB2 = Bb + (size_t)(tn + 128 + ar) * C_ + ag;

    const uint32_t sbase = smem_u32(smem);
    const uint32_t dA  = (ar * LDT + ag) * 2;
    const uint32_t dB2 = ((ar + 128) * LDT + ag) * 2;

    const int lA = laneA_off(lane);
    const int lB = laneB_off(lane);

    float acc[4][4][4];
    #pragma unroll
    for (int i = 0; i < 4; i++)
        #pragma unroll
        for (int j = 0; j < 4; j++)
            #pragma unroll
            for (int t = 0; t < 4; t++) acc[i][j][t] = 0.f;

    auto issueB = [&](int c) {
        const uint32_t sb = sbase + A_BYTES + (c % QB_NST) * QB_STAGE_BY;
        const int k0 = c * BK;
        cp16(sb + dA,  pB1 + k0);
        cp16(sb + dB2, pB2 + k0);
    };

    // A preload (16 slabs, 1 cp16/thread each) — rides in commit group 0
    {
        const __half* pA = Ahg + (size_t)(tm + ar) * C_ + ag;
        #pragma unroll
        for (int c = 0; c < QKV_NC; c++)
            cp16(sbase + c * ASLAB_BY + dA, pA + c * BK);
    }
    issueB(0);
    asm volatile("cp.async.commit_group;");
    issueB(1);
    asm volatile("cp.async.commit_group;");

    // prefetch depth 2 over 3 stages: issue(c+2) writes stage (c+2)%3 != c%3
    for (int c = 0; c < QKV_NC; ++c) {
        asm volatile("cp.async.wait_group 1;");
        __syncthreads();
        if (c + 2 < QKV_NC) issueB(c + 2);
        asm volatile("cp.async.commit_group;");

        const uint32_t aB = sbase + c * ASLAB_BY + (wm * LDT + lA) * 2;
        const uint32_t bB = sbase + A_BYTES + (c % QB_NST) * QB_STAGE_BY
                          + (wn * LDT + lB) * 2;
        compute_ks1(acc, aB,      bB);
        compute_ks1(acc, aB + 32, bB + 32);
    }

    // epilogue: hi always; lo only for q rows
    __half* chp = Ch + (size_t)blockIdx.z * O3 * N_;
    __half* clp = Cl + (size_t)blockIdx.z * O3 * N_;
    #pragma unroll
    for (int i = 0; i < 4; i++) {
        const int r0 = tm + wm + i * 16 + (lane >> 2);
        const float bv0 = bias[r0];
        const float bv1 = bias[r0 + 8];
        #pragma unroll
        for (int j = 0; j < 4; j++) {
            const int cc = tn + wn + j * 8 + (lane & 3) * 2;
            float d0 = acc[i][j][0] + bv0, d1 = acc[i][j][1] + bv0;
            float d2 = acc[i][j][2] + bv1, d3 = acc[i][j][3] + bv1;
            __half h0 = __float2half(d0), h1 = __float2half(d1);
            __half h2 = __float2half(d2), h3 = __float2half(d3);
            *reinterpret_cast<uint32_t*>(&chp[(size_t)r0 * N_ + cc])       = pack2h(h0, h1);
            *reinterpret_cast<uint32_t*>(&chp[(size_t)(r0 + 8) * N_ + cc]) = pack2h(h2, h3);
            if (wantLo) {
                __half l0 = __float2half(d0 - __half2float(h0));
                __half l1 = __float2half(d1 - __half2float(h1));
                __half l2 = __float2half(d2 - __half2float(h2));
                __half l3 = __float2half(d3 - __half2float(h3));
                *reinterpret_cast<uint32_t*>(&clp[(size_t)r0 * N_ + cc])       = pack2h(l0, l1);
                *reinterpret_cast<uint32_t*>(&clp[(size_t)(r0 + 8) * N_ + cc]) = pack2h(l2, l3);
            }
        }
    }
}

// ============== BIG kernel: 128x256, 512 thr, 3-stage =====================
// OUTMODE: 0 = f32, 1 = split hi/lo fp16 ; PASSES: 1 or 2
#define BM2 128
#define BN2 256
#define NST2 3
#define Q_AH 0
#define Q_AL (128 * LDT)
#define Q_BH (256 * LDT)
#define STAGE_EL2 (512 * LDT)
#define STAGE_BY2 (STAGE_EL2 * 2)             // 40960 B
#define SMEM_BY2 (NST2 * STAGE_BY2)           // 122880 B

template<bool HASBIAS, int OUTMODE, int PASSES>
__global__ __launch_bounds__(512)
void gemm_big(const __half* __restrict__ Ah, const __half* __restrict__ Al,
              const __half* __restrict__ Bh,
              float* __restrict__ Cf,
              __half* __restrict__ Ch, __half* __restrict__ Cl,
              const float* __restrict__ bias,
              int K, int lda, int ldb, int ldc,
              size_t sA_, size_t sB_, size_t sC_)
{
    extern __shared__ __half smem[];
    const int tid  = threadIdx.x;
    const int warp = tid >> 5;
    const int lane = tid & 31;
    const int wm   = (warp >> 3) * 64;
    const int wn   = (warp & 7) * 32;
    const int tm   = blockIdx.y * BM2;
    const int tn   = blockIdx.x * BN2;

    const __half* Ahb = Ah + (size_t)blockIdx.z * sA_;
    const __half* Alb = (PASSES == 2) ? Al + (size_t)blockIdx.z * sA_ : nullptr;
    const __half* Bhb = Bh + (size_t)blockIdx.z * sB_;

    const int arow = tid >> 2, ag = (tid & 3) * 8;

    const __half* pAh  = Ahb + (size_t)(tm + arow) * lda + ag;
    const __half* pAl  = (PASSES == 2) ? Alb + (size_t)(tm + arow) * lda + ag : nullptr;
    const __half* pB1h = Bhb + (size_t)(tn + arow) * ldb + ag;
    const __half* pB2h = Bhb + (size_t)(tn + 128 + arow) * ldb + ag;

    const uint32_t sbase = smem_u32(smem);
    const uint32_t dA  = (arow * LDT + ag) * 2;
    const uint32_t dB2 = ((arow + 128) * LDT + ag) * 2;

    const int lA = laneA_off(lane);
    const int lB = laneB_off(lane);

    float acc[4][4][4];
    #pragma unroll
    for (int i = 0; i < 4; i++)
        #pragma unroll
        for (int j = 0; j < 4; j++)
            #pragma unroll
            for (int t = 0; t < 4; t++) acc[i][j][t] = 0.f;

    auto issue = [&](int c) {
        const uint32_t sb = sbase + (c % NST2) * STAGE_BY2;
        const int k0 = c * BK;
        cp16(sb + Q_AH * 2 + dA,  pAh + k0);
        if (PASSES == 2) cp16(sb + Q_AL * 2 + dA, pAl + k0);
        cp16(sb + Q_BH * 2 + dA,  pB1h + k0);
        cp16(sb + Q_BH * 2 + dB2, pB2h + k0);
    };

    const int nc = K / BK;
    issue(0);
    asm volatile("cp.async.commit_group;");
    issue(1);
    asm volatile("cp.async.commit_group;");

    for (int c = 0; c < nc; ++c) {
        asm volatile("cp.async.wait_group 1;");
        __syncthreads();
        if (c + 2 < nc) issue(c + 2);
        asm volatile("cp.async.commit_group;");

        const uint32_t stb = sbase + (c % NST2) * STAGE_BY2;
        const uint32_t aH0 = stb + Q_AH * 2 + (wm * LDT + lA) * 2;
        const uint32_t aL0 = stb + Q_AL * 2 + (wm * LDT + lA) * 2;
        const uint32_t bH0 = stb + Q_BH * 2 + (wn * LDT + lB) * 2;
        #pragma unroll
        for (int ks = 0; ks < 2; ++ks) {
            const uint32_t ko = ks * 32;
            if (PASSES == 2) compute_ks2(acc, aH0 + ko, aL0 + ko, bH0 + ko);
            else             compute_ks1(acc, aH0 + ko, bH0 + ko);
        }
    }

    #pragma unroll
    for (int i = 0; i < 4; i++) {
        const int r0 = tm + wm + i * 16 + (lane >> 2);
        float bv0 = 0.f, bv1 = 0.f;
        if (HASBIAS) { bv0 = bias[r0]; bv1 = bias[r0 + 8]; }
        #pragma unroll
        for (int j = 0; j < 4; j++) {
            const int cc = tn + wn + j * 8 + (lane & 3) * 2;
            float d0 = acc[i][j][0] + bv0, d1 = acc[i][j][1] + bv0;
            float d2 = acc[i][j][2] + bv1, d3 = acc[i][j][3] + bv1;
            if (OUTMODE == 0) {
                float* cfp = Cf + (size_t)blockIdx.z * sC_;
                *reinterpret_cast<float2*>(&cfp[(size_t)r0 * ldc + cc])       = make_float2(d0, d1);
                *reinterpret_cast<float2*>(&cfp[(size_t)(r0 + 8) * ldc + cc]) = make_float2(d2, d3);
            } else {
                __half* chp = Ch + (size_t)blockIdx.z * sC_;
                __half* clp = Cl + (size_t)blockIdx.z * sC_;
                __half h0, h1, h2, h3, l0, l1, l2, l3;
                split2h(d0, h0, l0); split2h(d1, h1, l1);
                split2h(d2, h2, l2); split2h(d3, h3, l3);
                *reinterpret_cast<uint32_t*>(&chp[(size_t)r0 * ldc + cc])       = pack2h(h0, h1);
                *reinterpret_cast<uint32_t*>(&clp[(size_t)r0 * ldc + cc])       = pack2h(l0, l1);
                *reinterpret_cast<uint32_t*>(&chp[(size_t)(r0 + 8) * ldc + cc]) = pack2h(h2, h3);
                *reinterpret_cast<uint32_t*>(&clp[(size_t)(r0 + 8) * ldc + cc]) = pack2h(l2, l3);
            }
        }
    }
}

// ====== S kernel: 128x128, 256 thr, 2-stage, 2-pass, split-K ==============
#define SP_AH 0
#define SP_AL (128 * LDT)
#define SP_BH (256 * LDT)
#define STAGE_ELS (384 * LDT)
#define STAGE_BYS (STAGE_ELS * 2)             // 30720 B
#define NSTS 2
#define SMEM_BYS (NSTS * STAGE_BYS)           // 61440 B

__global__ __launch_bounds__(256)
void gemm_s(const __half* __restrict__ Ah, const __half* __restrict__ Al,
            const __half* __restrict__ Bh,
            float* __restrict__ Cf,
            int K, int lda, int ldb, int ldc,
            size_t sA_, size_t sB_, size_t sC_)
{
    extern __shared__ __half smem[];
    const int tid  = threadIdx.x;
    const int warp = tid >> 5;
    const int lane = tid & 31;
    const int wm   = (warp >> 2) * 64;
    const int wn   = (warp & 3) * 32;
    const int tm   = blockIdx.y * 128;
    const int tn   = blockIdx.x * 128;
    const int batch = blockIdx.z / KSPLIT;
    const int split = blockIdx.z % KSPLIT;
    const int kper  = K / KSPLIT;
    const int kbase = split * kper;

    const __half* Ahb = Ah + (size_t)batch * sA_ + kbase;
    const __half* Alb = Al + (size_t)batch * sA_ + kbase;
    const __half* Bhb = Bh + (size_t)batch * sB_ + kbase;

    const int lrow = tid >> 1;
    const int lg   = (tid & 1) * 16;
    const __half* pAh = Ahb + (size_t)(tm + lrow) * lda + lg;
    const __half* pAl = Alb + (size_t)(tm + lrow) * lda + lg;
    const __half* pBh = Bhb + (size_t)(tn + lrow) * ldb + lg;
    const uint32_t sbase = smem_u32(smem);
    const uint32_t doff  = (lrow * LDT + lg) * 2;

    const int lA = laneA_off(lane);
    const int lB = laneB_off(lane);

    float acc[4][4][4];
    #pragma unroll
    for (int i = 0; i < 4; i++)
        #pragma unroll
        for (int j = 0; j < 4; j++)
            #pragma unroll
            for (int t = 0; t < 4; t++) acc[i][j][t] = 0.f;

    auto issue = [&](int c) {
        const uint32_t sb = sbase + (c & 1) * STAGE_BYS + doff;
        const int k0 = c * BK;
        cp16(sb + SP_AH * 2,      pAh + k0);
        cp16(sb + SP_AH * 2 + 16, pAh + k0 + 8);
        cp16(sb + SP_AL * 2,      pAl + k0);
        cp16(sb + SP_AL * 2 + 16, pAl + k0 + 8);
        cp16(sb + SP_BH * 2,      pBh + k0);
        cp16(sb + SP_BH * 2 + 16, pBh + k0 + 8);
    };

    const int nc = kper / BK;
    issue(0);
    asm volatile("cp.async.commit_group;");

    for (int c = 0; c < nc; ++c) {
        asm volatile("cp.async.wait_group 0;");
        __syncthreads();
        if (c + 1 < nc) issue(c + 1);
        asm volatile("cp.async.commit_group;");

        const uint32_t stb = sbase + (c & 1) * STAGE_BYS;
        const uint32_t aH0 = stb + SP_AH * 2 + (wm * LDT + lA) * 2;
        const uint32_t aL0 = stb + SP_AL * 2 + (wm * LDT + lA) * 2;
        const uint32_t bH0 = stb + SP_BH * 2 + (wn * LDT + lB) * 2;
        #pragma unroll
        for (int ks = 0; ks < 2; ++ks) {
            const uint32_t ko = ks * 32;
            compute_ks2(acc, aH0 + ko, aL0 + ko, bH0 + ko);
        }
    }

    float* cfp = Cf + (size_t)split * B_ * C_ * C_ + (size_t)batch * sC_;
    #pragma unroll
    for (int i = 0; i < 4; i++) {
        const int r0 = tm + wm + i * 16 + (lane >> 2);
        #pragma unroll
        for (int j = 0; j < 4; j++) {
            const int cc = tn + wn + j * 8 + (lane & 3) * 2;
            *reinterpret_cast<float2*>(&cfp[(size_t)r0 * ldc + cc]) =
                make_float2(acc[i][j][0], acc[i][j][1]);
            *reinterpret_cast<float2*>(&cfp[(size_t)(r0 + 8) * ldc + cc]) =
                make_float2(acc[i][j][2], acc[i][j][3]);
        }
    }
}

// ------------- transpose fp32 [R,Cc] -> fp16 hi [Cc,R] ---------------------
__global__ void transpose_hi(const float* __restrict__ in,
                             __half* __restrict__ oh,
                             int R, int Cc, size_t sIn, size_t sOut)
{
    __shared__ float t[32][33];
    const float* ip = in + (size_t)blockIdx.z * sIn;
    int r0 = blockIdx.y * 32, c0 = blockIdx.x * 32;
    #pragma unroll
    for (int j = threadIdx.y; j < 32; j += 8)
        t[j][threadIdx.x] = ip[(size_t)(r0 + j) * Cc + c0 + threadIdx.x];
    __syncthreads();
    #pragma unroll
    for (int j = threadIdx.y; j < 32; j += 8) {
        size_t idx = (size_t)blockIdx.z * sOut + (size_t)(c0 + j) * R + r0 + threadIdx.x;
        oh[idx] = __float2half(t[threadIdx.x][j]);
    }
}

// ------------- transpose one fp16 plane: [R,Cc] -> [Cc,R] ------------------
__global__ void transpose_h1(const __half* __restrict__ ih,
                             __half* __restrict__ oh,
                             int R, int Cc, size_t sIn, size_t sOut)
{
    __shared__ __half t[32][34];
    const __half* ip = ih + (size_t)blockIdx.z * sIn;
    int r0 = blockIdx.y * 32, c0 = blockIdx.x * 32;
    #pragma unroll
    for (int j = threadIdx.y; j < 32; j += 8)
        t[j][threadIdx.x] = ip[(size_t)(r0 + j) * Cc + c0 + threadIdx.x];
    __syncthreads();
    #pragma unroll
    for (int j = threadIdx.y; j < 32; j += 8) {
        size_t d = (size_t)blockIdx.z * sOut + (size_t)(c0 + j) * R + r0 + threadIdx.x;
        oh[d] = t[threadIdx.x][j];
    }
}

// ------------- elementwise casts ------------------------------------------
__global__ void split_w(const float* __restrict__ in,
                        __half* __restrict__ oh,
                        __half* __restrict__ ol, int n)
{
    int i = blockIdx.x * blockDim.x + threadIdx.x;
    if (i >= n) return;
    __half h, l;
    split2h(in[i], h, l);
    oh[i] = h;
    ol[i] = l;
}
__global__ void cast_hi(const float* __restrict__ in,
                        __half* __restrict__ oh, int n)
{
    int i = blockIdx.x * blockDim.x + threadIdx.x;
    if (i >= n) return;
    oh[i] = __float2half(in[i]);
}

// ----- softmax over summed split-K partials (fp32 in x4, fp16 hi out) ------
__global__ void softmax_hi(const float* __restrict__ Sp,
                           __half* __restrict__ oh, float scale)
{
    int warp = (blockIdx.x * blockDim.x + threadIdx.x) >> 5;
    int lane = threadIdx.x & 31;
    if (warp >= B_ * C_) return;
    const size_t rowoff = (size_t)warp * C_;
    const size_t plane  = (size_t)B_ * C_ * C_;

    float vals[C_ / 32];
    float m = -1e30f;
    #pragma unroll
    for (int t = 0; t < C_ / 32; t++) {
        size_t idx = rowoff + lane + t * 32;
        float v = Sp[idx];
        v += Sp[idx + plane];
        v += Sp[idx + 2 * plane];
        v += Sp[idx + 3 * plane];
        vals[t] = v * scale;
        m = fmaxf(m, vals[t]);
    }
    #pragma unroll
    for (int o = 16; o; o >>= 1) m = fmaxf(m, __shfl_xor_sync(0xffffffffu, m, o));
    float s = 0.f;
    #pragma unroll
    for (int t = 0; t < C_ / 32; t++) { vals[t] = __expf(vals[t] - m); s += vals[t]; }
    #pragma unroll
    for (int o = 16; o; o >>= 1) s += __shfl_xor_sync(0xffffffffu, s, o);
    float inv = 1.f / s;
    #pragma unroll
    for (int t = 0; t < C_ / 32; t++)
        oh[rowoff + lane + t * 32] = __float2half(vals[t] * inv);
}

// ---------------- launcher ----------------
extern "C" void kernel_launch(void* const* d_in, const int* in_sizes, int n_in,
                              void* d_out, int out_size)
{
    const float* x      = (const float*)d_in[0];
    const float* w_qkv  = (const float*)d_in[1];
    const float* b_qkv  = (const float*)d_in[2];
    const float* w_proj = (const float*)d_in[3];
    const float* b_proj = (const float*)d_in[4];
    float* out = (float*)d_out;

    __half *qh, *ql, *xTh, *vTh, *ah, *aT, *Mh, *Ml, *wqh, *wph, *wpl;
    float *Sp;
    cudaGetSymbolAddress((void**)&qh,  g_qh);
    cudaGetSymbolAddress((void**)&ql,  g_ql);
    cudaGetSymbolAddress((void**)&xTh, g_xTh);
    cudaGetSymbolAddress((void**)&vTh, g_vTh);
    cudaGetSymbolAddress((void**)&Sp,  g_Sp);
    cudaGetSymbolAddress((void**)&ah,  g_ah);
    cudaGetSymbolAddress((void**)&aT,  g_aT);
    cudaGetSymbolAddress((void**)&Mh,  g_Mh);
    cudaGetSymbolAddress((void**)&Ml,  g_Ml);
    cudaGetSymbolAddress((void**)&wqh, g_wqh);
    cudaGetSymbolAddress((void**)&wph, g_wph);
    cudaGetSymbolAddress((void**)&wpl, g_wpl);

    cudaFuncSetAttribute(gemm_qkv, cudaFuncAttributeMaxDynamicSharedMemorySize, SMEM_QKV);
    cudaFuncSetAttribute(gemm_big<false, 1, 2>, cudaFuncAttributeMaxDynamicSharedMemorySize, SMEM_BY2);
    cudaFuncSetAttribute(gemm_big<true,  0, 2>, cudaFuncAttributeMaxDynamicSharedMemorySize, SMEM_BY2);
    cudaFuncSetAttribute(gemm_s, cudaFuncAttributeMaxDynamicSharedMemorySize, SMEM_BYS);

    const float scale = 1.0f / sqrtf((float)C_);
    dim3 tblk(32, 8);

    // 0) weights: qkv hi only (1-pass GEMM), proj hi/lo (2-pass GEMM)
    cast_hi<<<(O3 * C_ + 255) / 256, 256>>>(w_qkv, wqh, O3 * C_);
    split_w<<<(C_ * C_ + 255) / 256, 256>>>(w_proj, wph, wpl, C_ * C_);

    // 1) xT hi: x[b,c,n] -> [b,n,c]
    transpose_hi<<<dim3(N_ / 32, C_ / 32, B_), tblk>>>(
        x, xTh, C_, N_, (size_t)C_ * N_, (size_t)N_ * C_);

    // 2) qkv = w_qkv @ xT^T + b  (1-pass, A in smem) -> hi; lo for q rows only
    gemm_qkv<<<dim3(N_ / 256, O3 / 128, B_), 512, SMEM_QKV>>>(
        wqh, xTh, qh, ql, b_qkv);

    // 3) vT hi: v[b,d,n] -> [b,n,d]
    transpose_h1<<<dim3(N_ / 32, C_ / 32, B_), tblk>>>(
        qh + (size_t)2 * C_ * N_, vTh,
        C_, N_, (size_t)O3 * N_, (size_t)N_ * C_);

    // 4) S partials = q @ k^T (2-pass, split-K x4) -> fp32
    gemm_s<<<dim3(C_ / 128, C_ / 128, B_ * KSPLIT), 256, SMEM_BYS>>>(
        qh, ql, qh + (size_t)C_ * N_, Sp,
        N_, N_, N_, C_,
        (size_t)O3 * N_, (size_t)O3 * N_, (size_t)C_ * C_);

    // 5) softmax over summed partials -> attn hi
    softmax_hi<<<(B_ * C_ * 32 + 255) / 256, 256>>>(Sp, ah, scale);

    // 5b) attn^T: [c,d] -> [d,c]
    transpose_h1<<<dim3(C_ / 32, C_ / 32, B_), tblk>>>(
        ah, aT, C_, C_, (size_t)C_ * C_, (size_t)C_ * C_);

    // 6) M[b,o,d] = sum_c wp[o,c] * aT[d,c]  (2-pass) -> fp16 hi/lo
    gemm_big<false, 1, 2><<<dim3(C_ / BN2, C_ / BM2, B_), 512, SMEM_BY2>>>(
        wph, wpl, aT, nullptr, Mh, Ml, nullptr,
        C_, C_, C_, C_,
        0, (size_t)C_ * C_, (size_t)C_ * C_);

    // 7) out[b,o,n] = sum_d M[b,o,d] * vT[b,n,d] + b_proj  (2-pass) -> fp32
    gemm_big<true, 0, 2><<<dim3(N_ / BN2, C_ / BM2, B_), 512, SMEM_BY2>>>(
        Mh, Ml, vTh, out, nullptr, nullptr, b_proj,
        C_, C_, C_, N_,
        (size_t)C_ * C_, (size_t)N_ * C_, (size_t)C_ * N_);
}

// round 17
// speedup vs baseline: 1.9551x; 1.1481x over previous
#include <cuda_runtime.h>
#include <cuda_fp16.h>
#include <math.h>
#include <stdint.h>

// ---------------- problem constants ----------------
constexpr int B_ = 8, C_ = 512, H_ = 96, W_ = 96;
constexpr int N_ = H_ * W_;    // 9216
constexpr int O3 = 3 * C_;     // 1536
constexpr int QK = 2 * C_;     // 1024 (q,k rows only)
constexpr int KSPLIT = 4;

// ---------------- scratch ----------------
__device__ __align__(256) __half g_qh [(size_t)B_ * O3 * N_];   // q,k hi (v region unused)
__device__ __align__(256) __half g_ql [(size_t)B_ * O3 * N_];   // q lo
__device__ __align__(256) __half g_xTh[(size_t)B_ * N_ * C_];   // xT hi
__device__ __align__(256) float  g_Sp [(size_t)KSPLIT * B_ * C_ * C_];
__device__ __align__(256) __half g_ah [(size_t)B_ * C_ * C_];   // attn hi
__device__ __align__(256) __half g_aT [(size_t)B_ * C_ * C_];   // attn^T hi
__device__ __align__(256) __half g_Mh [(size_t)B_ * C_ * C_];   // M = wp@attn hi
__device__ __align__(256) __half g_Ml [(size_t)B_ * C_ * C_];   // M lo
__device__ __align__(256) __half g_W2h[(size_t)B_ * C_ * C_];   // W2 = M@wv hi
__device__ __align__(256) __half g_W2l[(size_t)B_ * C_ * C_];   // W2 lo
__device__ __align__(256) float  g_b2 [(size_t)B_ * C_];        // bias2
__device__ __align__(256) __half g_wqh [(size_t)O3 * C_];
__device__ __align__(256) __half g_wvTh[(size_t)C_ * C_];       // wv^T hi
__device__ __align__(256) __half g_wvTl[(size_t)C_ * C_];       // wv^T lo
__device__ __align__(256) __half g_wph [(size_t)C_ * C_];
__device__ __align__(256) __half g_wpl [(size_t)C_ * C_];

// ---------------- common helpers ----------------
#define BK 32
#define LDT 40

__device__ __forceinline__ uint32_t smem_u32(const void* p) {
    uint32_t a;
    asm("{ .reg .u64 t; cvta.to.shared.u64 t, %1; cvt.u32.u64 %0, t; }"
        : "=r"(a) : "l"(p));
    return a;
}
__device__ __forceinline__ void cp16(uint32_t dst, const void* src) {
    asm volatile("cp.async.cg.shared.global [%0], [%1], 16;"
                 :: "r"(dst), "l"(src));
}
__device__ __forceinline__ void mma16816(float* d, const uint32_t* a,
                                         const uint32_t* b) {
    asm volatile(
        "mma.sync.aligned.m16n8k16.row.col.f32.f16.f16.f32 "
        "{%0,%1,%2,%3}, {%4,%5,%6,%7}, {%8,%9}, {%0,%1,%2,%3};"
        : "+f"(d[0]), "+f"(d[1]), "+f"(d[2]), "+f"(d[3])
        : "r"(a[0]), "r"(a[1]), "r"(a[2]), "r"(a[3]), "r"(b[0]), "r"(b[1]));
}
__device__ __forceinline__ void ldm4(uint32_t* r, uint32_t a) {
    asm volatile("ldmatrix.sync.aligned.m8n8.x4.shared.b16 {%0,%1,%2,%3}, [%4];"
        : "=r"(r[0]), "=r"(r[1]), "=r"(r[2]), "=r"(r[3]) : "r"(a));
}
__device__ __forceinline__ uint32_t pack2h(__half a, __half b) {
    return (uint32_t)__half_as_ushort(a) |
           ((uint32_t)__half_as_ushort(b) << 16);
}
__device__ __forceinline__ void split2h(float f, __half& h, __half& l) {
    h = __float2half(f);
    l = __float2half(f - __half2float(h));
}
__device__ __forceinline__ int laneA_off(int lane) {
    return ((lane & 7) + ((lane >> 3) & 1) * 8) * LDT + ((lane >> 4) & 1) * 8;
}
__device__ __forceinline__ int laneB_off(int lane) {
    return ((lane & 7) + ((lane >> 4) & 1) * 8) * LDT + ((lane >> 3) & 1) * 8;
}

// 1-pass: ah*bh
__device__ __forceinline__ void compute_ks1(float acc[4][4][4],
                                            uint32_t aHi, uint32_t bHi)
{
    uint32_t ah[4][4], bh[2][4];
    #pragma unroll
    for (int i = 0; i < 4; i++) ldm4(ah[i], aHi + i * (16 * LDT * 2));
    #pragma unroll
    for (int jp = 0; jp < 2; jp++) ldm4(bh[jp], bHi + jp * (16 * LDT * 2));
    #pragma unroll
    for (int i = 0; i < 4; i++) {
        mma16816(acc[i][0], ah[i], bh[0]);
        mma16816(acc[i][1], ah[i], bh[0] + 2);
        mma16816(acc[i][2], ah[i], bh[1]);
        mma16816(acc[i][3], ah[i], bh[1] + 2);
    }
}

// 2-pass: (ah+al)*bh
__device__ __forceinline__ void compute_ks2(float acc[4][4][4],
                                            uint32_t aHi, uint32_t aLo,
                                            uint32_t bHi)
{
    uint32_t ah[4][4], al_[4][4], bh[2][4];
    #pragma unroll
    for (int i = 0; i < 4; i++) ldm4(ah[i], aHi + i * (16 * LDT * 2));
    #pragma unroll
    for (int jp = 0; jp < 2; jp++) ldm4(bh[jp], bHi + jp * (16 * LDT * 2));
    #pragma unroll
    for (int i = 0; i < 4; i++) {
        ldm4(al_[i], aLo + i * (16 * LDT * 2));
        mma16816(acc[i][0], ah[i], bh[0]);
        mma16816(acc[i][1], ah[i], bh[0] + 2);
        mma16816(acc[i][2], ah[i], bh[1]);
        mma16816(acc[i][3], ah[i], bh[1] + 2);
    }
    #pragma unroll
    for (int i = 0; i < 4; i++) {
        mma16816(acc[i][0], al_[i], bh[0]);
        mma16816(acc[i][1], al_[i], bh[0] + 2);
        mma16816(acc[i][2], al_[i], bh[1]);
        mma16816(acc[i][3], al_[i], bh[1] + 2);
    }
}

// 3-pass: (ah+al)*bh + ah*bl
__device__ __forceinline__ void compute_ks3(float acc[4][4][4],
                                            uint32_t aHi, uint32_t aLo,
                                            uint32_t bHi, uint32_t bLo)
{
    uint32_t ah[4][4], al_[4][4], bh[2][4], bl_[2][4];
    #pragma unroll
    for (int i = 0; i < 4; i++) ldm4(ah[i], aHi + i * (16 * LDT * 2));
    #pragma unroll
    for (int jp = 0; jp < 2; jp++) ldm4(bh[jp], bHi + jp * (16 * LDT * 2));
    #pragma unroll
    for (int i = 0; i < 4; i++) {
        ldm4(al_[i], aLo + i * (16 * LDT * 2));
        mma16816(acc[i][0], ah[i], bh[0]);
        mma16816(acc[i][1], ah[i], bh[0] + 2);
        mma16816(acc[i][2], ah[i], bh[1]);
        mma16816(acc[i][3], ah[i], bh[1] + 2);
    }
    #pragma unroll
    for (int i = 0; i < 4; i++) {
        if (i < 2) ldm4(bl_[i], bLo + i * (16 * LDT * 2));
        mma16816(acc[i][0], al_[i], bh[0]);
        mma16816(acc[i][1], al_[i], bh[0] + 2);
        mma16816(acc[i][2], al_[i], bh[1]);
        mma16816(acc[i][3], al_[i], bh[1] + 2);
    }
    #pragma unroll
    for (int i = 0; i < 4; i++) {
        mma16816(acc[i][0], ah[i], bl_[0]);
        mma16816(acc[i][1], ah[i], bl_[0] + 2);
        mma16816(acc[i][2], ah[i], bl_[1]);
        mma16816(acc[i][3], ah[i], bl_[1] + 2);
    }
}

// ============== QKV kernel: q,k rows only; A (weights) resident in smem ====
#define QKV_NC 16
#define ASLAB_BY (128 * LDT * 2)               // 10240 B
#define A_BYTES (QKV_NC * ASLAB_BY)            // 163840 B
#define QB_STAGE_BY (256 * LDT * 2)            // 20480 B
#define QB_NST 3
#define SMEM_QKV (A_BYTES + QB_NST * QB_STAGE_BY)   // 225280 B

__global__ __launch_bounds__(512)
void gemm_qkv(const __half* __restrict__ Ahg, const __half* __restrict__ Bhg,
              __half* __restrict__ Ch, __half* __restrict__ Cl,
              const float* __restrict__ bias)
{
    extern __shared__ __half smem[];
    const int tid  = threadIdx.x;
    const int warp = tid >> 5;
    const int lane = tid & 31;
    const int wm   = (warp >> 3) * 64;
    const int wn   = (warp & 7) * 32;
    const int tm   = blockIdx.y * 128;
    const int tn   = blockIdx.x * 256;
    const bool wantLo = (blockIdx.y < 4);

    const __half* Bb = Bhg + (size_t)blockIdx.z * N_ * C_;

    const int ar = tid >> 2, ag = (tid & 3) * 8;
    const __half* pB1 = Bb + (size_t)(tn + ar) * C_ + ag;
    const __half* pB2 = Bb + (size_t)(tn + 128 + ar) * C_ + ag;

    const uint32_t sbase = smem_u32(smem);
    const uint32_t dA  = (ar * LDT + ag) * 2;
    const uint32_t dB2 = ((ar + 128) * LDT + ag) * 2;

    const int lA = laneA_off(lane);
    const int lB = laneB_off(lane);

    float acc[4][4][4];
    #pragma unroll
    for (int i = 0; i < 4; i++)
        #pragma unroll
        for (int j = 0; j < 4; j++)
            #pragma unroll
            for (int t = 0; t < 4; t++) acc[i][j][t] = 0.f;

    auto issueB = [&](int c) {
        const uint32_t sb = sbase + A_BYTES + (c % QB_NST) * QB_STAGE_BY;
        const int k0 = c * BK;
        cp16(sb + dA,  pB1 + k0);
        cp16(sb + dB2, pB2 + k0);
    };

    {
        const __half* pA = Ahg + (size_t)(tm + ar) * C_ + ag;
        #pragma unroll
        for (int c = 0; c < QKV_NC; c++)
            cp16(sbase + c * ASLAB_BY + dA, pA + c * BK);
    }
    issueB(0);
    asm volatile("cp.async.commit_group;");
    issueB(1);
    asm volatile("cp.async.commit_group;");

    for (int c = 0; c < QKV_NC; ++c) {
        asm volatile("cp.async.wait_group 1;");
        __syncthreads();
        if (c + 2 < QKV_NC) issueB(c + 2);
        asm volatile("cp.async.commit_group;");

        const uint32_t aB = sbase + c * ASLAB_BY + (wm * LDT + lA) * 2;
        const uint32_t bB = sbase + A_BYTES + (c % QB_NST) * QB_STAGE_BY
                          + (wn * LDT + lB) * 2;
        compute_ks1(acc, aB,      bB);
        compute_ks1(acc, aB + 32, bB + 32);
    }

    __half* chp = Ch + (size_t)blockIdx.z * O3 * N_;
    __half* clp = Cl + (size_t)blockIdx.z * O3 * N_;
    #pragma unroll
    for (int i = 0; i < 4; i++) {
        const int r0 = tm + wm + i * 16 + (lane >> 2);
        const float bv0 = bias[r0];
        const float bv1 = bias[r0 + 8];
        #pragma unroll
        for (int j = 0; j < 4; j++) {
            const int cc = tn + wn + j * 8 + (lane & 3) * 2;
            float d0 = acc[i][j][0] + bv0, d1 = acc[i][j][1] + bv0;
            float d2 = acc[i][j][2] + bv1, d3 = acc[i][j][3] + bv1;
            __half h0 = __float2half(d0), h1 = __float2half(d1);
            __half h2 = __float2half(d2), h3 = __float2half(d3);
            *reinterpret_cast<uint32_t*>(&chp[(size_t)r0 * N_ + cc])       = pack2h(h0, h1);
            *reinterpret_cast<uint32_t*>(&chp[(size_t)(r0 + 8) * N_ + cc]) = pack2h(h2, h3);
            if (wantLo) {
                __half l0 = __float2half(d0 - __half2float(h0));
                __half l1 = __float2half(d1 - __half2float(h1));
                __half l2 = __float2half(d2 - __half2float(h2));
                __half l3 = __float2half(d3 - __half2float(h3));
                *reinterpret_cast<uint32_t*>(&clp[(size_t)r0 * N_ + cc])       = pack2h(l0, l1);
                *reinterpret_cast<uint32_t*>(&clp[(size_t)(r0 + 8) * N_ + cc]) = pack2h(l2, l3);
            }
        }
    }
}

// ============== BIG kernel: 128x256, 512 thr, 3-stage =====================
// OUTMODE: 0 = f32, 1 = split hi/lo fp16 ; PASSES: 1, 2, or 3
#define BM2 128
#define BN2 256
#define NST2 3

template<bool HASBIAS, int OUTMODE, int PASSES>
__global__ __launch_bounds__(512)
void gemm_big(const __half* __restrict__ Ah, const __half* __restrict__ Al,
              const __half* __restrict__ Bh, const __half* __restrict__ Bl,
              float* __restrict__ Cf,
              __half* __restrict__ Ch, __half* __restrict__ Cl,
              const float* __restrict__ bias, size_t sBias,
              int K, int lda, int ldb, int ldc,
              size_t sA_, size_t sB_, size_t sC_)
{
    constexpr uint32_t P_AL = 128 * LDT * 2;
    constexpr uint32_t P_BH = 256 * LDT * 2;
    constexpr uint32_t P_BL = 512 * LDT * 2;
    constexpr int SROWS = (PASSES == 3) ? 768 : 512;
    constexpr uint32_t STAGE_BY = (uint32_t)SROWS * LDT * 2;

    extern __shared__ __half smem[];
    const int tid  = threadIdx.x;
    const int warp = tid >> 5;
    const int lane = tid & 31;
    const int wm   = (warp >> 3) * 64;
    const int wn   = (warp & 7) * 32;
    const int tm   = blockIdx.y * BM2;
    const int tn   = blockIdx.x * BN2;

    const __half* Ahb = Ah + (size_t)blockIdx.z * sA_;
    const __half* Alb = (PASSES >= 2) ? Al + (size_t)blockIdx.z * sA_ : nullptr;
    const __half* Bhb = Bh + (size_t)blockIdx.z * sB_;
    const __half* Blb = (PASSES == 3) ? Bl + (size_t)blockIdx.z * sB_ : nullptr;

    const int arow = tid >> 2, ag = (tid & 3) * 8;

    const __half* pAh  = Ahb + (size_t)(tm + arow) * lda + ag;
    const __half* pAl  = (PASSES >= 2) ? Alb + (size_t)(tm + arow) * lda + ag : nullptr;
    const __half* pB1h = Bhb + (size_t)(tn + arow) * ldb + ag;
    const __half* pB2h = Bhb + (size_t)(tn + 128 + arow) * ldb + ag;
    const __half* pB1l = (PASSES == 3) ? Blb + (size_t)(tn + arow) * ldb + ag : nullptr;
    const __half* pB2l = (PASSES == 3) ? Blb + (size_t)(tn + 128 + arow) * ldb + ag : nullptr;

    const uint32_t sbase = smem_u32(smem);
    const uint32_t dA  = (arow * LDT + ag) * 2;
    const uint32_t dB2 = ((arow + 128) * LDT + ag) * 2;

    const int lA = laneA_off(lane);
    const int lB = laneB_off(lane);

    float acc[4][4][4];
    #pragma unroll
    for (int i = 0; i < 4; i++)
        #pragma unroll
        for (int j = 0; j < 4; j++)
            #pragma unroll
            for (int t = 0; t < 4; t++) acc[i][j][t] = 0.f;

    auto issue = [&](int c) {
        const uint32_t sb = sbase + (c % NST2) * STAGE_BY;
        const int k0 = c * BK;
        cp16(sb + dA, pAh + k0);
        if (PASSES >= 2) cp16(sb + P_AL + dA, pAl + k0);
        cp16(sb + P_BH + dA,  pB1h + k0);
        cp16(sb + P_BH + dB2, pB2h + k0);
        if (PASSES == 3) {
            cp16(sb + P_BL + dA,  pB1l + k0);
            cp16(sb + P_BL + dB2, pB2l + k0);
        }
    };

    const int nc = K / BK;
    issue(0);
    asm volatile("cp.async.commit_group;");
    issue(1);
    asm volatile("cp.async.commit_group;");

    for (int c = 0; c < nc; ++c) {
        asm volatile("cp.async.wait_group 1;");
        __syncthreads();
        if (c + 2 < nc) issue(c + 2);
        asm volatile("cp.async.commit_group;");

        const uint32_t stb = sbase + (c % NST2) * STAGE_BY;
        const uint32_t aH0 = stb + (wm * LDT + lA) * 2;
        const uint32_t aL0 = stb + P_AL + (wm * LDT + lA) * 2;
        const uint32_t bH0 = stb + P_BH + (wn * LDT + lB) * 2;
        const uint32_t bL0 = stb + P_BL + (wn * LDT + lB) * 2;
        #pragma unroll
        for (int ks = 0; ks < 2; ++ks) {
            const uint32_t ko = ks * 32;
            if (PASSES == 3)      compute_ks3(acc, aH0 + ko, aL0 + ko, bH0 + ko, bL0 + ko);
            else if (PASSES == 2) compute_ks2(acc, aH0 + ko, aL0 + ko, bH0 + ko);
            else                  compute_ks1(acc, aH0 + ko, bH0 + ko);
        }
    }

    const float* biasp = HASBIAS ? bias + blockIdx.z * sBias : nullptr;
    #pragma unroll
    for (int i = 0; i < 4; i++) {
        const int r0 = tm + wm + i * 16 + (lane >> 2);
        float bv0 = 0.f, bv1 = 0.f;
        if (HASBIAS) { bv0 = biasp[r0]; bv1 = biasp[r0 + 8]; }
        #pragma unroll
        for (int j = 0; j < 4; j++) {
            const int cc = tn + wn + j * 8 + (lane & 3) * 2;
            float d0 = acc[i][j][0] + bv0, d1 = acc[i][j][1] + bv0;
            float d2 = acc[i][j][2] + bv1, d3 = acc[i][j][3] + bv1;
            if (OUTMODE == 0) {
                float* cfp = Cf + (size_t)blockIdx.z * sC_;
                *reinterpret_cast<float2*>(&cfp[(size_t)r0 * ldc + cc])       = make_float2(d0, d1);
                *reinterpret_cast<float2*>(&cfp[(size_t)(r0 + 8) * ldc + cc]) = make_float2(d2, d3);
            } else {
                __half* chp = Ch + (size_t)blockIdx.z * sC_;
                __half* clp = Cl + (size_t)blockIdx.z * sC_;
                __half h0, h1, h2, h3, l0, l1, l2, l3;
                split2h(d0, h0, l0); split2h(d1, h1, l1);
                split2h(d2, h2, l2); split2h(d3, h3, l3);
                *reinterpret_cast<uint32_t*>(&chp[(size_t)r0 * ldc + cc])       = pack2h(h0, h1);
                *reinterpret_cast<uint32_t*>(&clp[(size_t)r0 * ldc + cc])       = pack2h(l0, l1);
                *reinterpret_cast<uint32_t*>(&chp[(size_t)(r0 + 8) * ldc + cc]) = pack2h(h2, h3);
                *reinterpret_cast<uint32_t*>(&clp[(size_t)(r0 + 8) * ldc + cc]) = pack2h(l2, l3);
            }
        }
    }
}

// ====== S kernel: 128x128, 256 thr, 2-stage, 2-pass, split-K ==============
#define SP_AH 0
#define SP_AL (128 * LDT)
#define SP_BH (256 * LDT)
#define STAGE_ELS (384 * LDT)
#define STAGE_BYS (STAGE_ELS * 2)
#define SMEM_BYS (2 * STAGE_BYS)

__global__ __launch_bounds__(256)
void gemm_s(const __half* __restrict__ Ah, const __half* __restrict__ Al,
            const __half* __restrict__ Bh,
            float* __restrict__ Cf,
            int K, int lda, int ldb, int ldc,
            size_t sA_, size_t sB_, size_t sC_)
{
    extern __shared__ __half smem[];
    const int tid  = threadIdx.x;
    const int warp = tid >> 5;
    const int lane = tid & 31;
    const int wm   = (warp >> 2) * 64;
    const int wn   = (warp & 3) * 32;
    const int tm   = blockIdx.y * 128;
    const int tn   = blockIdx.x * 128;
    const int batch = blockIdx.z / KSPLIT;
    const int split = blockIdx.z % KSPLIT;
    const int kper  = K / KSPLIT;
    const int kbase = split * kper;

    const __half* Ahb = Ah + (size_t)batch * sA_ + kbase;
    const __half* Alb = Al + (size_t)batch * sA_ + kbase;
    const __half* Bhb = Bh + (size_t)batch * sB_ + kbase;

    const int lrow = tid >> 1;
    const int lg   = (tid & 1) * 16;
    const __half* pAh = Ahb + (size_t)(tm + lrow) * lda + lg;
    const __half* pAl = Alb + (size_t)(tm + lrow) * lda + lg;
    const __half* pBh = Bhb + (size_t)(tn + lrow) * ldb + lg;
    const uint32_t sbase = smem_u32(smem);
    const uint32_t doff  = (lrow * LDT + lg) * 2;

    const int lA = laneA_off(lane);
    const int lB = laneB_off(lane);

    float acc[4][4][4];
    #pragma unroll
    for (int i = 0; i < 4; i++)
        #pragma unroll
        for (int j = 0; j < 4; j++)
            #pragma unroll
            for (int t = 0; t < 4; t++) acc[i][j][t] = 0.f;

    auto issue = [&](int c) {
        const uint32_t sb = sbase + (c & 1) * STAGE_BYS + doff;
        const int k0 = c * BK;
        cp16(sb + SP_AH * 2,      pAh + k0);
        cp16(sb + SP_AH * 2 + 16, pAh + k0 + 8);
        cp16(sb + SP_AL * 2,      pAl + k0);
        cp16(sb + SP_AL * 2 + 16, pAl + k0 + 8);
        cp16(sb + SP_BH * 2,      pBh + k0);
        cp16(sb + SP_BH * 2 + 16, pBh + k0 + 8);
    };

    const int nc = kper / BK;
    issue(0);
    asm volatile("cp.async.commit_group;");

    for (int c = 0; c < nc; ++c) {
        asm volatile("cp.async.wait_group 0;");
        __syncthreads();
        if (c + 1 < nc) issue(c + 1);
        asm volatile("cp.async.commit_group;");

        const uint32_t stb = sbase + (c & 1) * STAGE_BYS;
        const uint32_t aH0 = stb + SP_AH * 2 + (wm * LDT + lA) * 2;
        const uint32_t aL0 = stb + SP_AL * 2 + (wm * LDT + lA) * 2;
        const uint32_t bH0 = stb + SP_BH * 2 + (wn * LDT + lB) * 2;
        #pragma unroll
        for (int ks = 0; ks < 2; ++ks) {
            const uint32_t ko = ks * 32;
            compute_ks2(acc, aH0 + ko, aL0 + ko, bH0 + ko);
        }
    }

    float* cfp = Cf + (size_t)split * B_ * C_ * C_ + (size_t)batch * sC_;
    #pragma unroll
    for (int i = 0; i < 4; i++) {
        const int r0 = tm + wm + i * 16 + (lane >> 2);
        #pragma unroll
        for (int j = 0; j < 4; j++) {
            const int cc = tn + wn + j * 8 + (lane & 3) * 2;
            *reinterpret_cast<float2*>(&cfp[(size_t)r0 * ldc + cc]) =
                make_float2(acc[i][j][0], acc[i][j][1]);
            *reinterpret_cast<float2*>(&cfp[(size_t)(r0 + 8) * ldc + cc]) =
                make_float2(acc[i][j][2], acc[i][j][3]);
        }
    }
}

// ------------- transpose fp32 [R,Cc] -> fp16 hi [Cc,R] ---------------------
__global__ void transpose_hi(const float* __restrict__ in,
                             __half* __restrict__ oh,
                             int R, int Cc, size_t sIn, size_t sOut)
{
    __shared__ float t[32][33];
    const float* ip = in + (size_t)blockIdx.z * sIn;
    int r0 = blockIdx.y * 32, c0 = blockIdx.x * 32;
    #pragma unroll
    for (int j = threadIdx.y; j < 32; j += 8)
        t[j][threadIdx.x] = ip[(size_t)(r0 + j) * Cc + c0 + threadIdx.x];
    __syncthreads();
    #pragma unroll
    for (int j = threadIdx.y; j < 32; j += 8) {
        size_t idx = (size_t)blockIdx.z * sOut + (size_t)(c0 + j) * R + r0 + threadIdx.x;
        oh[idx] = __float2half(t[threadIdx.x][j]);
    }
}

// ------------- transpose fp32 [R,Cc] -> fp16 hi/lo [Cc,R] ------------------
__global__ void transpose_split(const float* __restrict__ in,
                                __half* __restrict__ oh,
                                __half* __restrict__ ol,
                                int R, int Cc)
{
    __shared__ float t[32][33];
    int r0 = blockIdx.y * 32, c0 = blockIdx.x * 32;
    #pragma unroll
    for (int j = threadIdx.y; j < 32; j += 8)
        t[j][threadIdx.x] = in[(size_t)(r0 + j) * Cc + c0 + threadIdx.x];
    __syncthreads();
    #pragma unroll
    for (int j = threadIdx.y; j < 32; j += 8) {
        float f = t[threadIdx.x][j];
        __half h, l;
        split2h(f, h, l);
        size_t idx = (size_t)(c0 + j) * R + r0 + threadIdx.x;
        oh[idx] = h;
        ol[idx] = l;
    }
}

// ------------- transpose one fp16 plane: [R,Cc] -> [Cc,R] ------------------
__global__ void transpose_h1(const __half* __restrict__ ih,
                             __half* __restrict__ oh,
                             int R, int Cc, size_t sIn, size_t sOut)
{
    __shared__ __half t[32][34];
    const __half* ip = ih + (size_t)blockIdx.z * sIn;
    int r0 = blockIdx.y * 32, c0 = blockIdx.x * 32;
    #pragma unroll
    for (int j = threadIdx.y; j < 32; j += 8)
        t[j][threadIdx.x] = ip[(size_t)(r0 + j) * Cc + c0 + threadIdx.x];
    __syncthreads();
    #pragma unroll
    for (int j = threadIdx.y; j < 32; j += 8) {
        size_t d = (size_t)blockIdx.z * sOut + (size_t)(c0 + j) * R + r0 + threadIdx.x;
        oh[d] = t[threadIdx.x][j];
    }
}

// ------------- elementwise casts ------------------------------------------
__global__ void split_w(const float* __restrict__ in,
                        __half* __restrict__ oh,
                        __half* __restrict__ ol, int n)
{
    int i = blockIdx.x * blockDim.x + threadIdx.x;
    if (i >= n) return;
    __half h, l;
    split2h(in[i], h, l);
    oh[i] = h;
    ol[i] = l;
}
__global__ void cast_hi(const float* __restrict__ in,
                        __half* __restrict__ oh, int n)
{
    int i = blockIdx.x * blockDim.x + threadIdx.x;
    if (i >= n) return;
    oh[i] = __float2half(in[i]);
}

// ----- bias2[b,o] = b_proj[o] + sum_d (Mh+Ml)[b,o,d] * bv[d] ---------------
__global__ void bias2_kernel(const __half* __restrict__ Mh,
                             const __half* __restrict__ Ml,
                             const float* __restrict__ bqkv,
                             const float* __restrict__ bproj,
                             float* __restrict__ b2)
{
    int gw = (blockIdx.x * blockDim.x + threadIdx.x) >> 5;
    int lane = threadIdx.x & 31;
    if (gw >= B_ * C_) return;
    int o = gw % C_;
    const __half* mh = Mh + (size_t)gw * C_;
    const __half* ml = Ml + (size_t)gw * C_;
    const float* bv = bqkv + 2 * C_;
    float s = 0.f;
    #pragma unroll 4
    for (int d = lane; d < C_; d += 32)
        s += (__half2float(mh[d]) + __half2float(ml[d])) * bv[d];
    #pragma unroll
    for (int off = 16; off; off >>= 1) s += __shfl_xor_sync(0xffffffffu, s, off);
    if (lane == 0) b2[gw] = s + bproj[o];
}

// ----- softmax over summed split-K partials (fp32 in x4, fp16 hi out) ------
__global__ void softmax_hi(const float* __restrict__ Sp,
                           __half* __restrict__ oh, float scale)
{
    int warp = (blockIdx.x * blockDim.x + threadIdx.x) >> 5;
    int lane = threadIdx.x & 31;
    if (warp >= B_ * C_) return;
    const size_t rowoff = (size_t)warp * C_;
    const size_t plane  = (size_t)B_ * C_ * C_;

    float vals[C_ / 32];
    float m = -1e30f;
    #pragma unroll
    for (int t = 0; t < C_ / 32; t++) {
        size_t idx = rowoff + lane + t * 32;
        float v = Sp[idx];
        v += Sp[idx + plane];
        v += Sp[idx + 2 * plane];
        v += Sp[idx + 3 * plane];
        vals[t] = v * scale;
        m = fmaxf(m, vals[t]);
    }
    #pragma unroll
    for (int o = 16; o; o >>= 1) m = fmaxf(m, __shfl_xor_sync(0xffffffffu, m, o));
    float s = 0.f;
    #pragma unroll
    for (int t = 0; t < C_ / 32; t++) { vals[t] = __expf(vals[t] - m); s += vals[t]; }
    #pragma unroll
    for (int o = 16; o; o >>= 1) s += __shfl_xor_sync(0xffffffffu, s, o);
    float inv = 1.f / s;
    #pragma unroll
    for (int t = 0; t < C_ / 32; t++)
        oh[rowoff + lane + t * 32] = __float2half(vals[t] * inv);
}

// ---------------- launcher ----------------
extern "C" void kernel_launch(void* const* d_in, const int* in_sizes, int n_in,
                              void* d_out, int out_size)
{
    const float* x      = (const float*)d_in[0];
    const float* w_qkv  = (const float*)d_in[1];
    const float* b_qkv  = (const float*)d_in[2];
    const float* w_proj = (const float*)d_in[3];
    const float* b_proj = (const float*)d_in[4];
    float* out = (float*)d_out;

    __half *qh, *ql, *xTh, *ah, *aT, *Mh, *Ml, *W2h, *W2l, *wqh, *wvTh, *wvTl, *wph, *wpl;
    float *Sp, *b2;
    cudaGetSymbolAddress((void**)&qh,   g_qh);
    cudaGetSymbolAddress((void**)&ql,   g_ql);
    cudaGetSymbolAddress((void**)&xTh,  g_xTh);
    cudaGetSymbolAddress((void**)&Sp,   g_Sp);
    cudaGetSymbolAddress((void**)&ah,   g_ah);
    cudaGetSymbolAddress((void**)&aT,   g_aT);
    cudaGetSymbolAddress((void**)&Mh,   g_Mh);
    cudaGetSymbolAddress((void**)&Ml,   g_Ml);
    cudaGetSymbolAddress((void**)&W2h,  g_W2h);
    cudaGetSymbolAddress((void**)&W2l,  g_W2l);
    cudaGetSymbolAddress((void**)&b2,   g_b2);
    cudaGetSymbolAddress((void**)&wqh,  g_wqh);
    cudaGetSymbolAddress((void**)&wvTh, g_wvTh);
    cudaGetSymbolAddress((void**)&wvTl, g_wvTl);
    cudaGetSymbolAddress((void**)&wph,  g_wph);
    cudaGetSymbolAddress((void**)&wpl,  g_wpl);

    const int SM_P2 = 3 * 512 * LDT * 2;   // 122880
    const int SM_P3 = 3 * 768 * LDT * 2;   // 184320
    cudaFuncSetAttribute(gemm_qkv, cudaFuncAttributeMaxDynamicSharedMemorySize, SMEM_QKV);
    cudaFuncSetAttribute(gemm_big<false, 1, 2>, cudaFuncAttributeMaxDynamicSharedMemorySize, SM_P2);
    cudaFuncSetAttribute(gemm_big<false, 1, 3>, cudaFuncAttributeMaxDynamicSharedMemorySize, SM_P3);
    cudaFuncSetAttribute(gemm_big<true,  0, 2>, cudaFuncAttributeMaxDynamicSharedMemorySize, SM_P2);
    cudaFuncSetAttribute(gemm_s, cudaFuncAttributeMaxDynamicSharedMemorySize, SMEM_BYS);

    const float scale = 1.0f / sqrtf((float)C_);
    dim3 tblk(32, 8);

    // 0) weights
    cast_hi<<<(O3 * C_ + 255) / 256, 256>>>(w_qkv, wqh, O3 * C_);
    split_w<<<(C_ * C_ + 255) / 256, 256>>>(w_proj, wph, wpl, C_ * C_);
    transpose_split<<<dim3(C_ / 32, C_ / 32, 1), tblk>>>(
        w_qkv + (size_t)2 * C_ * C_, wvTh, wvTl, C_, C_);

    // 1) xT hi
    transpose_hi<<<dim3(N_ / 32, C_ / 32, B_), tblk>>>(
        x, xTh, C_, N_, (size_t)C_ * N_, (size_t)N_ * C_);

    // 2) q,k = w_qkv[0:2C] @ xT^T + b  (1-pass, A in smem)
    gemm_qkv<<<dim3(N_ / 256, QK / 128, B_), 512, SMEM_QKV>>>(
        wqh, xTh, qh, ql, b_qkv);

    // 3) S partials = q @ k^T (2-pass, split-K x4)
    gemm_s<<<dim3(C_ / 128, C_ / 128, B_ * KSPLIT), 256, SMEM_BYS>>>(
        qh, ql, qh + (size_t)C_ * N_, Sp,
        N_, N_, N_, C_,
        (size_t)O3 * N_, (size_t)O3 * N_, (size_t)C_ * C_);

    // 4) softmax -> attn hi
    softmax_hi<<<(B_ * C_ * 32 + 255) / 256, 256>>>(Sp, ah, scale);

    // 4b) attn^T
    transpose_h1<<<dim3(C_ / 32, C_ / 32, B_), tblk>>>(
        ah, aT, C_, C_, (size_t)C_ * C_, (size_t)C_ * C_);

    // 5) M = wp @ attn (2-pass) -> hi/lo
    gemm_big<false, 1, 2><<<dim3(C_ / BN2, C_ / BM2, B_), 512, SM_P2>>>(
        wph, wpl, aT, nullptr, nullptr, Mh, Ml, nullptr, 0,
        C_, C_, C_, C_,
        0, (size_t)C_ * C_, (size_t)C_ * C_);

    // 6) W2 = M @ wv (3-pass) -> hi/lo.  D[o,e] = sum_d M[o,d] * wvT[e,d]
    gemm_big<false, 1, 3><<<dim3(C_ / BN2, C_ / BM2, B_), 512, SM_P3>>>(
        Mh, Ml, wvTh, wvTl, nullptr, W2h, W2l, nullptr, 0,
        C_, C_, C_, C_,
        (size_t)C_ * C_, 0, (size_t)C_ * C_);

    // 6b) bias2 = M @ bv + b_proj
    bias2_kernel<<<(B_ * C_ * 32 + 255) / 256, 256>>>(Mh, Ml, b_qkv, b_proj, b2);

    // 7) out = W2 @ xT^T + bias2 (2-pass) -> fp32
    gemm_big<true, 0, 2><<<dim3(N_ / BN2, C_ / BM2, B_), 512, SM_P2>>>(
        W2h, W2l, xTh, nullptr, out, nullptr, nullptr, b2, C_,
        C_, C_, C_, N_,
        (size_t)C_ * C_, (size_t)N_ * C_, (size_t)C_ * N_);
}